// round 2
// baseline (speedup 1.0000x reference)
#include <cuda_runtime.h>
#include <math.h>

#define BATCH 2
#define SEQ   2048
#define DIM   2048
#define NH    16
#define NKV   4
#define HD    128
#define KVDIM (NKV * HD)      // 512
#define ROWS  (BATCH * SEQ)   // 4096

// Scratch (device globals: allocation-free per harness rules)
static __device__ float g_q[(size_t)ROWS * DIM];     // 32 MB
static __device__ float g_k[(size_t)ROWS * KVDIM];   //  8 MB
static __device__ float g_v[(size_t)ROWS * KVDIM];   //  8 MB
static __device__ float g_att[(size_t)ROWS * DIM];   // 32 MB

// ---------------------------------------------------------------------------
// SGEMM: C[M,N] = A[M,K] @ B[K,N], 128x128 block, BK=8, 256 threads, 8x8/thread.
// Column register mapping is strided (col = tx + 16*j) so Bs reads are scalar,
// bank-conflict-free; As reads are float4 broadcasts.
// Requires M%128==0, N%128==0, K%8==0 (true for all our shapes).
// ---------------------------------------------------------------------------
__global__ __launch_bounds__(256, 2) void sgemm_k(const float* __restrict__ A,
                                                  const float* __restrict__ B,
                                                  float* __restrict__ C,
                                                  int M, int N, int K)
{
    __shared__ float As[8][128];   // transposed: As[k][m]
    __shared__ float Bs[8][128];   // Bs[k][n]

    const int tid = threadIdx.x;
    const int tx  = tid & 15;      // col group
    const int ty  = tid >> 4;      // row group
    const int bm  = blockIdx.y * 128;
    const int bn  = blockIdx.x * 128;

    float acc[8][8];
    #pragma unroll
    for (int i = 0; i < 8; i++)
        #pragma unroll
        for (int j = 0; j < 8; j++) acc[i][j] = 0.0f;

    const int ar = tid >> 1;            // A tile row   (0..127)
    const int ac = (tid & 1) * 4;       // A tile k-col (0 or 4)
    const int br = tid >> 5;            // B tile k-row (0..7)
    const int bc = (tid & 31) * 4;      // B tile col   (0..124)

    for (int k0 = 0; k0 < K; k0 += 8) {
        float4 av = *(const float4*)(A + (size_t)(bm + ar) * K + k0 + ac);
        float4 bv = *(const float4*)(B + (size_t)(k0 + br) * N + bn + bc);
        As[ac + 0][ar] = av.x;
        As[ac + 1][ar] = av.y;
        As[ac + 2][ar] = av.z;
        As[ac + 3][ar] = av.w;
        *(float4*)&Bs[br][bc] = bv;
        __syncthreads();

        #pragma unroll
        for (int kk = 0; kk < 8; ++kk) {
            float ra[8], rb[8];
            *(float4*)&ra[0] = *(const float4*)&As[kk][ty * 8];
            *(float4*)&ra[4] = *(const float4*)&As[kk][ty * 8 + 4];
            #pragma unroll
            for (int j = 0; j < 8; j++) rb[j] = Bs[kk][tx + 16 * j];
            #pragma unroll
            for (int i = 0; i < 8; i++)
                #pragma unroll
                for (int j = 0; j < 8; j++)
                    acc[i][j] = fmaf(ra[i], rb[j], acc[i][j]);
        }
        __syncthreads();
    }

    #pragma unroll
    for (int i = 0; i < 8; i++) {
        float* cr = C + (size_t)(bm + ty * 8 + i) * N + bn + tx;
        #pragma unroll
        for (int j = 0; j < 8; j++) cr[16 * j] = acc[i][j];
    }
}

// ---------------------------------------------------------------------------
// RoPE, replicating the reference's swapped-argument call:
//   f_cos = sin(angle), f_sin = cos(angle)
//   re' = re*sin - im*cos ; im' = re*cos + im*sin
// Angle range-reduced in double so accuracy survives --use_fast_math.
// ---------------------------------------------------------------------------
__global__ void rope_k(float* __restrict__ d, int rowlen, int npairs)
{
    int idx = blockIdx.x * blockDim.x + threadIdx.x;
    if (idx >= npairs) return;
    const int pr  = rowlen >> 1;
    const int row = idx / pr;
    const int col = (idx - row * pr) * 2;
    const int p   = (col & (HD - 1)) >> 1;  // pair index within head (0..63)
    const int s   = row & (SEQ - 1);        // token position

    // freq = 10000^(-p/64) = 2^(-p * log2(10000)/64)
    float freq = exp2f(-(float)p * 0.2076205059304640f);
    double angd = (double)s * (double)freq;
    double kturns = floor(angd * 0.15915494309189535);          // / (2*pi)
    float ang = (float)(angd - kturns * 6.283185307179586);
    float sn, cs;
    sincosf(ang, &sn, &cs);

    float* ptr = d + (size_t)row * rowlen + col;
    float re = ptr[0];
    float im = ptr[1];
    ptr[0] = re * sn - im * cs;
    ptr[1] = re * cs + im * sn;
}

// ---------------------------------------------------------------------------
// Flash attention: BR=BC=64, 256 threads (16x16), fp32, online softmax.
// Thread (ty,tx): scores s[i][j] at (row ty*4+i, col tx+16*j)
//                 output  o[i][c] at (row ty*4+i, col tx+16*c)
// GQA: head h reads kv head h>>2. Causal mask only on diagonal tile.
// Smem: Qs/Ks/Vs [64][129] (pad 1 word -> conflict-free strided reads),
//       Ps [64][65]. Total 115712 B dynamic.
// ---------------------------------------------------------------------------
#define FL_SMEM_FLOATS (3 * 64 * 129 + 64 * 65)

__global__ __launch_bounds__(256, 2) void flash_k(const float* __restrict__ Qg,
                                                  const float* __restrict__ Kg,
                                                  const float* __restrict__ Vg,
                                                  float* __restrict__ Og)
{
    extern __shared__ float sm[];
    float* Qs = sm;                   // [64][129]
    float* Ks = Qs + 64 * 129;        // [64][129]
    float* Vs = Ks + 64 * 129;        // [64][129]
    float* Ps = Vs + 64 * 129;        // [64][65]

    const int tid = threadIdx.x;
    const int tx  = tid & 15;
    const int ty  = tid >> 4;
    const int b   = blockIdx.z;
    const int h   = blockIdx.y;
    const int q0  = blockIdx.x * 64;
    const int kvh = h >> 2;
    const float scale = 0.08838834764831845f;  // 1/sqrt(128)

    const float* Qb = Qg + (size_t)b * SEQ * DIM + h * HD;
    const float* Kb = Kg + (size_t)b * SEQ * KVDIM + kvh * HD;
    const float* Vb = Vg + (size_t)b * SEQ * KVDIM + kvh * HD;

    // Load Q tile, pre-scaled by 1/sqrt(HD)
    for (int i = tid; i < 64 * 32; i += 256) {
        int r = i >> 5, dg = (i & 31) << 2;
        float4 v = *(const float4*)(Qb + (size_t)(q0 + r) * DIM + dg);
        float* qp = Qs + r * 129 + dg;
        qp[0] = v.x * scale; qp[1] = v.y * scale;
        qp[2] = v.z * scale; qp[3] = v.w * scale;
    }

    float o[4][8];
    #pragma unroll
    for (int i = 0; i < 4; i++)
        #pragma unroll
        for (int c = 0; c < 8; c++) o[i][c] = 0.0f;
    float mi[4], li[4];
    #pragma unroll
    for (int i = 0; i < 4; i++) { mi[i] = -1e30f; li[i] = 0.0f; }

    const int ntiles = (q0 >> 6) + 1;
    for (int kt = 0; kt < ntiles; ++kt) {
        const int j0 = kt * 64;
        __syncthreads();  // prev iter's reads of Ks/Vs/Ps done; Q store visible
        for (int i = tid; i < 64 * 32; i += 256) {
            int r = i >> 5, dg = (i & 31) << 2;
            float4 kv4 = *(const float4*)(Kb + (size_t)(j0 + r) * KVDIM + dg);
            float* kp = Ks + r * 129 + dg;
            kp[0] = kv4.x; kp[1] = kv4.y; kp[2] = kv4.z; kp[3] = kv4.w;
            float4 vv4 = *(const float4*)(Vb + (size_t)(j0 + r) * KVDIM + dg);
            float* vp = Vs + r * 129 + dg;
            vp[0] = vv4.x; vp[1] = vv4.y; vp[2] = vv4.z; vp[3] = vv4.w;
        }
        __syncthreads();

        // S = Q @ K^T
        float s[4][4];
        #pragma unroll
        for (int i = 0; i < 4; i++)
            #pragma unroll
            for (int j = 0; j < 4; j++) s[i][j] = 0.0f;
        #pragma unroll 4
        for (int d = 0; d < 128; ++d) {
            float qv[4], kv[4];
            #pragma unroll
            for (int i = 0; i < 4; i++) qv[i] = Qs[(ty * 4 + i) * 129 + d];
            #pragma unroll
            for (int j = 0; j < 4; j++) kv[j] = Ks[(tx + 16 * j) * 129 + d];
            #pragma unroll
            for (int i = 0; i < 4; i++)
                #pragma unroll
                for (int j = 0; j < 4; j++)
                    s[i][j] = fmaf(qv[i], kv[j], s[i][j]);
        }

        if (kt == ntiles - 1) {  // diagonal tile: causal mask
            #pragma unroll
            for (int i = 0; i < 4; i++) {
                int ig = q0 + ty * 4 + i;
                #pragma unroll
                for (int j = 0; j < 4; j++) {
                    int jg = j0 + tx + 16 * j;
                    if (jg > ig) s[i][j] = -1e30f;
                }
            }
        }

        // Online softmax; row spans the 16 tx-lanes (16-lane xor shuffles)
        #pragma unroll
        for (int i = 0; i < 4; i++) {
            float rm = s[i][0];
            #pragma unroll
            for (int j = 1; j < 4; j++) rm = fmaxf(rm, s[i][j]);
            #pragma unroll
            for (int off = 8; off > 0; off >>= 1)
                rm = fmaxf(rm, __shfl_xor_sync(0xffffffffu, rm, off));
            float mn = fmaxf(mi[i], rm);
            float alpha = __expf(mi[i] - mn);
            mi[i] = mn;
            float rs = 0.0f;
            #pragma unroll
            for (int j = 0; j < 4; j++) {
                s[i][j] = __expf(s[i][j] - mn);
                rs += s[i][j];
            }
            #pragma unroll
            for (int off = 8; off > 0; off >>= 1)
                rs += __shfl_xor_sync(0xffffffffu, rs, off);
            li[i] = li[i] * alpha + rs;
            #pragma unroll
            for (int c = 0; c < 8; c++) o[i][c] *= alpha;
            #pragma unroll
            for (int j = 0; j < 4; j++)
                Ps[(ty * 4 + i) * 65 + tx + 16 * j] = s[i][j];
        }
        __syncthreads();

        // O += P @ V
        #pragma unroll 2
        for (int j = 0; j < 64; ++j) {
            float pv[4], vv[8];
            #pragma unroll
            for (int i = 0; i < 4; i++) pv[i] = Ps[(ty * 4 + i) * 65 + j];
            #pragma unroll
            for (int c = 0; c < 8; c++) vv[c] = Vs[j * 129 + tx + 16 * c];
            #pragma unroll
            for (int i = 0; i < 4; i++)
                #pragma unroll
                for (int c = 0; c < 8; c++)
                    o[i][c] = fmaf(pv[i], vv[c], o[i][c]);
        }
    }

    // Epilogue: O /= l, write in (B,S,H*HD) layout (matches reference transpose)
    #pragma unroll
    for (int i = 0; i < 4; i++) {
        float inv = 1.0f / li[i];
        float* op = Og + (size_t)(b * SEQ + q0 + ty * 4 + i) * DIM + h * HD + tx;
        #pragma unroll
        for (int c = 0; c < 8; c++) op[16 * c] = o[i][c] * inv;
    }
}

// ---------------------------------------------------------------------------
extern "C" void kernel_launch(void* const* d_in, const int* in_sizes, int n_in,
                              void* d_out, int out_size)
{
    const float* x  = (const float*)d_in[0];
    const float* wq = (const float*)d_in[1];
    const float* wk = (const float*)d_in[2];
    const float* wv = (const float*)d_in[3];
    const float* w0 = (const float*)d_in[4];
    float* out = (float*)d_out;

    float *q, *k, *v, *att;
    cudaGetSymbolAddress((void**)&q, g_q);
    cudaGetSymbolAddress((void**)&k, g_k);
    cudaGetSymbolAddress((void**)&v, g_v);
    cudaGetSymbolAddress((void**)&att, g_att);

    // QKV projections
    sgemm_k<<<dim3(DIM / 128, ROWS / 128), 256>>>(x, wq, q, ROWS, DIM, DIM);
    sgemm_k<<<dim3(KVDIM / 128, ROWS / 128), 256>>>(x, wk, k, ROWS, KVDIM, DIM);
    sgemm_k<<<dim3(KVDIM / 128, ROWS / 128), 256>>>(x, wv, v, ROWS, KVDIM, DIM);

    // RoPE on q and k
    {
        int npq = ROWS * DIM / 2;
        rope_k<<<(npq + 255) / 256, 256>>>(q, DIM, npq);
        int npk = ROWS * KVDIM / 2;
        rope_k<<<(npk + 255) / 256, 256>>>(k, KVDIM, npk);
    }

    // Flash attention
    {
        size_t smem = (size_t)FL_SMEM_FLOATS * sizeof(float);  // 115712 B
        cudaFuncSetAttribute(flash_k, cudaFuncAttributeMaxDynamicSharedMemorySize,
                             (int)smem);
        flash_k<<<dim3(SEQ / 64, NH, BATCH), 256, smem>>>(q, k, v, att);
    }

    // Output projection
    sgemm_k<<<dim3(DIM / 128, ROWS / 128), 256>>>(att, w0, out, ROWS, DIM, DIM);
}

// round 6
// speedup vs baseline: 1.6646x; 1.6646x over previous
#include <cuda_runtime.h>
#include <cstdint>
#include <math.h>

#define BATCH 2
#define SEQ   2048
#define DIM   2048
#define NH    16
#define NKV   4
#define HD    128
#define KVDIM (NKV * HD)      // 512
#define ROWS  (BATCH * SEQ)   // 4096

// Scratch (device globals: allocation-free per harness rules)
static __device__ float g_q[(size_t)ROWS * DIM];       // 32 MB
static __device__ float g_k[(size_t)ROWS * KVDIM];     //  8 MB
static __device__ float g_v[(size_t)ROWS * KVDIM];     //  8 MB
static __device__ float g_att[(size_t)ROWS * DIM];     // 32 MB
static __device__ float g_wqT[(size_t)DIM * DIM];      // 16 MB  [N,K] tf32-rounded
static __device__ float g_wkT[(size_t)KVDIM * DIM];    //  4 MB
static __device__ float g_wvT[(size_t)KVDIM * DIM];    //  4 MB
static __device__ float g_w0T[(size_t)DIM * DIM];      // 16 MB

__device__ __forceinline__ uint32_t f2tf32(float x) {
    uint32_t r;
    asm("cvt.rna.tf32.f32 %0, %1;" : "=r"(r) : "f"(x));
    return r;
}

__device__ __forceinline__ void mma_tf32(float& c0, float& c1, float& c2, float& c3,
                                         uint32_t a0, uint32_t a1, uint32_t a2, uint32_t a3,
                                         uint32_t b0, uint32_t b1) {
    asm volatile(
        "mma.sync.aligned.m16n8k8.row.col.f32.tf32.tf32.f32 "
        "{%0,%1,%2,%3}, {%4,%5,%6,%7}, {%8,%9}, {%0,%1,%2,%3};"
        : "+f"(c0), "+f"(c1), "+f"(c2), "+f"(c3)
        : "r"(a0), "r"(a1), "r"(a2), "r"(a3), "r"(b0), "r"(b1));
}

// ---------------------------------------------------------------------------
// Transpose + tf32(RNE) round: W[K,N] row-major -> WT[N,K] row-major
// ---------------------------------------------------------------------------
__global__ void transpose_tf32_k(const float* __restrict__ W,
                                 float* __restrict__ WT, int K, int N)
{
    __shared__ float t[32][33];
    int x = blockIdx.x * 32 + threadIdx.x;  // N
    int y = blockIdx.y * 32 + threadIdx.y;  // K
    #pragma unroll
    for (int i = 0; i < 32; i += 8)
        t[threadIdx.y + i][threadIdx.x] = W[(size_t)(y + i) * N + x];
    __syncthreads();
    int xo = blockIdx.y * 32 + threadIdx.x;  // K
    int yo = blockIdx.x * 32 + threadIdx.y;  // N
    uint32_t* O = (uint32_t*)WT;
    #pragma unroll
    for (int i = 0; i < 32; i += 8)
        O[(size_t)(yo + i) * K + xo] = f2tf32(t[threadIdx.x][threadIdx.y + i]);
}

// ---------------------------------------------------------------------------
// Tensor-core tf32 GEMM via mma.sync:  C[M,N] = A[M,K] @ BT[N,K]^T
// A fp32 (RNE-rounded to tf32 at staging); BT pre-rounded tf32.
// CTA tile 128x128, BK=16, 256 threads (8 warps, 2x4), warp tile 64x32.
// Smem [128][20] padding -> conflict-free fragment loads.
// Requires M%128==0, N%128==0, K%16==0.
// ---------------------------------------------------------------------------
__global__ __launch_bounds__(256, 2) void tc_gemm(const float* __restrict__ A,
                                                  const float* __restrict__ BT,
                                                  float* __restrict__ C,
                                                  int M, int N, int K)
{
    __shared__ float As[2][128][20];
    __shared__ float Bs[2][128][20];

    const int tid = threadIdx.x;
    const int wid = tid >> 5;
    const int lane = tid & 31;
    const int g  = lane >> 2;        // group 0..7
    const int t4 = lane & 3;         // thread-in-group 0..3
    const int wm = (wid >> 2) * 64;  // warp m offset 0/64
    const int wn = (wid & 3) * 32;   // warp n offset 0/32/64/96
    const int bm = blockIdx.y * 128;
    const int bn = blockIdx.x * 128;

    // Global-load mapping: 512 float4 per operand tile, 2 per thread
    const int lr = tid >> 2;         // row 0..63 (and +64)
    const int lc = (tid & 3) * 4;    // k-col 0/4/8/12

    float c[4][4][4];                // [mt][nt][reg]
    #pragma unroll
    for (int mt = 0; mt < 4; mt++)
        #pragma unroll
        for (int nt = 0; nt < 4; nt++)
            #pragma unroll
            for (int r = 0; r < 4; r++) c[mt][nt][r] = 0.0f;

    const int nk = K >> 4;

    // Preload tile 0
    {
        const float* Ap = A + (size_t)bm * K;
        const float* Bp = BT + (size_t)bn * K;
        #pragma unroll
        for (int h = 0; h < 2; h++) {
            int r = lr + 64 * h;
            float4 av = *(const float4*)(Ap + (size_t)r * K + lc);
            uint4 au;
            au.x = f2tf32(av.x); au.y = f2tf32(av.y);
            au.z = f2tf32(av.z); au.w = f2tf32(av.w);
            *(uint4*)&As[0][r][lc] = au;
            *(float4*)&Bs[0][r][lc] = *(const float4*)(Bp + (size_t)r * K + lc);
        }
    }
    __syncthreads();

    for (int tIt = 0; tIt < nk; ++tIt) {
        const int cur = tIt & 1;
        const int nxt = cur ^ 1;
        const bool more = (tIt + 1) < nk;

        // Issue next tile's global loads early
        float4 an[2], bnx[2];
        if (more) {
            const int k0 = (tIt + 1) << 4;
            const float* Ap = A + (size_t)bm * K + k0;
            const float* Bp = BT + (size_t)bn * K + k0;
            #pragma unroll
            for (int h = 0; h < 2; h++) {
                int r = lr + 64 * h;
                an[h]  = *(const float4*)(Ap + (size_t)r * K + lc);
                bnx[h] = *(const float4*)(Bp + (size_t)r * K + lc);
            }
        }

        // Compute: two k=8 substeps
        #pragma unroll
        for (int kk = 0; kk < 16; kk += 8) {
            uint32_t af[4][4];
            #pragma unroll
            for (int mt = 0; mt < 4; mt++) {
                int r0 = wm + mt * 16 + g;
                af[mt][0] = __float_as_uint(As[cur][r0][kk + t4]);
                af[mt][1] = __float_as_uint(As[cur][r0 + 8][kk + t4]);
                af[mt][2] = __float_as_uint(As[cur][r0][kk + t4 + 4]);
                af[mt][3] = __float_as_uint(As[cur][r0 + 8][kk + t4 + 4]);
            }
            uint32_t bf[4][2];
            #pragma unroll
            for (int nt = 0; nt < 4; nt++) {
                int n0 = wn + nt * 8 + g;
                bf[nt][0] = __float_as_uint(Bs[cur][n0][kk + t4]);
                bf[nt][1] = __float_as_uint(Bs[cur][n0][kk + t4 + 4]);
            }
            #pragma unroll
            for (int mt = 0; mt < 4; mt++)
                #pragma unroll
                for (int nt = 0; nt < 4; nt++)
                    mma_tf32(c[mt][nt][0], c[mt][nt][1], c[mt][nt][2], c[mt][nt][3],
                             af[mt][0], af[mt][1], af[mt][2], af[mt][3],
                             bf[nt][0], bf[nt][1]);
        }

        // Stage next tile
        if (more) {
            #pragma unroll
            for (int h = 0; h < 2; h++) {
                int r = lr + 64 * h;
                uint4 au;
                au.x = f2tf32(an[h].x); au.y = f2tf32(an[h].y);
                au.z = f2tf32(an[h].z); au.w = f2tf32(an[h].w);
                *(uint4*)&As[nxt][r][lc] = au;
                *(float4*)&Bs[nxt][r][lc] = bnx[h];
            }
        }
        __syncthreads();
    }

    // Epilogue: c0,c1 at (row, col..col+1), c2,c3 at (row+8, ...)
    #pragma unroll
    for (int mt = 0; mt < 4; mt++) {
        int row = bm + wm + mt * 16 + g;
        #pragma unroll
        for (int nt = 0; nt < 4; nt++) {
            int col = bn + wn + nt * 8 + t4 * 2;
            float2 v0 = make_float2(c[mt][nt][0], c[mt][nt][1]);
            float2 v1 = make_float2(c[mt][nt][2], c[mt][nt][3]);
            *(float2*)(C + (size_t)row * N + col) = v0;
            *(float2*)(C + (size_t)(row + 8) * N + col) = v1;
        }
    }
}

// ---------------------------------------------------------------------------
// RoPE, replicating the reference's swapped-argument call:
//   re' = re*sin - im*cos ; im' = re*cos + im*sin
// ---------------------------------------------------------------------------
__global__ void rope_k(float* __restrict__ d, int rowlen, int npairs)
{
    int idx = blockIdx.x * blockDim.x + threadIdx.x;
    if (idx >= npairs) return;
    const int pr  = rowlen >> 1;
    const int row = idx / pr;
    const int col = (idx - row * pr) * 2;
    const int p   = (col & (HD - 1)) >> 1;
    const int s   = row & (SEQ - 1);

    float freq = exp2f(-(float)p * 0.2076205059304640f);
    double angd = (double)s * (double)freq;
    double kturns = floor(angd * 0.15915494309189535);
    float ang = (float)(angd - kturns * 6.283185307179586);
    float sn, cs;
    sincosf(ang, &sn, &cs);

    float* ptr = d + (size_t)row * rowlen + col;
    float re = ptr[0];
    float im = ptr[1];
    ptr[0] = re * sn - im * cs;
    ptr[1] = re * cs + im * sn;
}

// ---------------------------------------------------------------------------
// Flash attention (fp32, unchanged from R1 passing version)
// ---------------------------------------------------------------------------
#define FL_SMEM_FLOATS (3 * 64 * 129 + 64 * 65)

__global__ __launch_bounds__(256, 2) void flash_k(const float* __restrict__ Qg,
                                                  const float* __restrict__ Kg,
                                                  const float* __restrict__ Vg,
                                                  float* __restrict__ Og)
{
    extern __shared__ float smf[];
    float* Qs = smf;
    float* Ks = Qs + 64 * 129;
    float* Vs = Ks + 64 * 129;
    float* Ps = Vs + 64 * 129;

    const int tid = threadIdx.x;
    const int tx  = tid & 15;
    const int ty  = tid >> 4;
    const int b   = blockIdx.z;
    const int h   = blockIdx.y;
    const int q0  = blockIdx.x * 64;
    const int kvh = h >> 2;
    const float scale = 0.08838834764831845f;

    const float* Qb = Qg + (size_t)b * SEQ * DIM + h * HD;
    const float* Kb = Kg + (size_t)b * SEQ * KVDIM + kvh * HD;
    const float* Vb = Vg + (size_t)b * SEQ * KVDIM + kvh * HD;

    for (int i = tid; i < 64 * 32; i += 256) {
        int r = i >> 5, dg = (i & 31) << 2;
        float4 v = *(const float4*)(Qb + (size_t)(q0 + r) * DIM + dg);
        float* qp = Qs + r * 129 + dg;
        qp[0] = v.x * scale; qp[1] = v.y * scale;
        qp[2] = v.z * scale; qp[3] = v.w * scale;
    }

    float o[4][8];
    #pragma unroll
    for (int i = 0; i < 4; i++)
        #pragma unroll
        for (int c = 0; c < 8; c++) o[i][c] = 0.0f;
    float mi[4], li[4];
    #pragma unroll
    for (int i = 0; i < 4; i++) { mi[i] = -1e30f; li[i] = 0.0f; }

    const int ntiles = (q0 >> 6) + 1;
    for (int kt = 0; kt < ntiles; ++kt) {
        const int j0 = kt * 64;
        __syncthreads();
        for (int i = tid; i < 64 * 32; i += 256) {
            int r = i >> 5, dg = (i & 31) << 2;
            float4 kv4 = *(const float4*)(Kb + (size_t)(j0 + r) * KVDIM + dg);
            float* kp = Ks + r * 129 + dg;
            kp[0] = kv4.x; kp[1] = kv4.y; kp[2] = kv4.z; kp[3] = kv4.w;
            float4 vv4 = *(const float4*)(Vb + (size_t)(j0 + r) * KVDIM + dg);
            float* vp = Vs + r * 129 + dg;
            vp[0] = vv4.x; vp[1] = vv4.y; vp[2] = vv4.z; vp[3] = vv4.w;
        }
        __syncthreads();

        float s[4][4];
        #pragma unroll
        for (int i = 0; i < 4; i++)
            #pragma unroll
            for (int j = 0; j < 4; j++) s[i][j] = 0.0f;
        #pragma unroll 4
        for (int d = 0; d < 128; ++d) {
            float qv[4], kv[4];
            #pragma unroll
            for (int i = 0; i < 4; i++) qv[i] = Qs[(ty * 4 + i) * 129 + d];
            #pragma unroll
            for (int j = 0; j < 4; j++) kv[j] = Ks[(tx + 16 * j) * 129 + d];
            #pragma unroll
            for (int i = 0; i < 4; i++)
                #pragma unroll
                for (int j = 0; j < 4; j++)
                    s[i][j] = fmaf(qv[i], kv[j], s[i][j]);
        }

        if (kt == ntiles - 1) {
            #pragma unroll
            for (int i = 0; i < 4; i++) {
                int ig = q0 + ty * 4 + i;
                #pragma unroll
                for (int j = 0; j < 4; j++) {
                    int jg = j0 + tx + 16 * j;
                    if (jg > ig) s[i][j] = -1e30f;
                }
            }
        }

        #pragma unroll
        for (int i = 0; i < 4; i++) {
            float rm = s[i][0];
            #pragma unroll
            for (int j = 1; j < 4; j++) rm = fmaxf(rm, s[i][j]);
            #pragma unroll
            for (int off = 8; off > 0; off >>= 1)
                rm = fmaxf(rm, __shfl_xor_sync(0xffffffffu, rm, off));
            float mn = fmaxf(mi[i], rm);
            float alpha = __expf(mi[i] - mn);
            mi[i] = mn;
            float rs = 0.0f;
            #pragma unroll
            for (int j = 0; j < 4; j++) {
                s[i][j] = __expf(s[i][j] - mn);
                rs += s[i][j];
            }
            #pragma unroll
            for (int off = 8; off > 0; off >>= 1)
                rs += __shfl_xor_sync(0xffffffffu, rs, off);
            li[i] = li[i] * alpha + rs;
            #pragma unroll
            for (int c = 0; c < 8; c++) o[i][c] *= alpha;
            #pragma unroll
            for (int j = 0; j < 4; j++)
                Ps[(ty * 4 + i) * 65 + tx + 16 * j] = s[i][j];
        }
        __syncthreads();

        #pragma unroll 2
        for (int j = 0; j < 64; ++j) {
            float pv[4], vv[8];
            #pragma unroll
            for (int i = 0; i < 4; i++) pv[i] = Ps[(ty * 4 + i) * 65 + j];
            #pragma unroll
            for (int c = 0; c < 8; c++) vv[c] = Vs[j * 129 + tx + 16 * c];
            #pragma unroll
            for (int i = 0; i < 4; i++)
                #pragma unroll
                for (int c = 0; c < 8; c++)
                    o[i][c] = fmaf(pv[i], vv[c], o[i][c]);
        }
    }

    #pragma unroll
    for (int i = 0; i < 4; i++) {
        float inv = 1.0f / li[i];
        float* op = Og + (size_t)(b * SEQ + q0 + ty * 4 + i) * DIM + h * HD + tx;
        #pragma unroll
        for (int c = 0; c < 8; c++) op[16 * c] = o[i][c] * inv;
    }
}

// ---------------------------------------------------------------------------
extern "C" void kernel_launch(void* const* d_in, const int* in_sizes, int n_in,
                              void* d_out, int out_size)
{
    const float* x  = (const float*)d_in[0];
    const float* wq = (const float*)d_in[1];
    const float* wk = (const float*)d_in[2];
    const float* wv = (const float*)d_in[3];
    const float* w0 = (const float*)d_in[4];
    float* out = (float*)d_out;

    float *q, *k, *v, *att, *wqT, *wkT, *wvT, *w0T;
    cudaGetSymbolAddress((void**)&q,   g_q);
    cudaGetSymbolAddress((void**)&k,   g_k);
    cudaGetSymbolAddress((void**)&v,   g_v);
    cudaGetSymbolAddress((void**)&att, g_att);
    cudaGetSymbolAddress((void**)&wqT, g_wqT);
    cudaGetSymbolAddress((void**)&wkT, g_wkT);
    cudaGetSymbolAddress((void**)&wvT, g_wvT);
    cudaGetSymbolAddress((void**)&w0T, g_w0T);

    // Transpose + tf32-round all weights
    {
        dim3 blk(32, 8);
        transpose_tf32_k<<<dim3(DIM / 32,   DIM / 32), blk>>>(wq, wqT, DIM, DIM);
        transpose_tf32_k<<<dim3(KVDIM / 32, DIM / 32), blk>>>(wk, wkT, DIM, KVDIM);
        transpose_tf32_k<<<dim3(KVDIM / 32, DIM / 32), blk>>>(wv, wvT, DIM, KVDIM);
        transpose_tf32_k<<<dim3(DIM / 32,   DIM / 32), blk>>>(w0, w0T, DIM, DIM);
    }

    // QKV projections (tensor-core tf32)
    tc_gemm<<<dim3(DIM / 128,   ROWS / 128), 256>>>(x, wqT, q, ROWS, DIM, DIM);
    tc_gemm<<<dim3(KVDIM / 128, ROWS / 128), 256>>>(x, wkT, k, ROWS, KVDIM, DIM);
    tc_gemm<<<dim3(KVDIM / 128, ROWS / 128), 256>>>(x, wvT, v, ROWS, KVDIM, DIM);

    // RoPE on q and k
    {
        int npq = ROWS * DIM / 2;
        rope_k<<<(npq + 255) / 256, 256>>>(q, DIM, npq);
        int npk = ROWS * KVDIM / 2;
        rope_k<<<(npk + 255) / 256, 256>>>(k, KVDIM, npk);
    }

    // Flash attention (fp32)
    {
        size_t smem = (size_t)FL_SMEM_FLOATS * sizeof(float);
        cudaFuncSetAttribute(flash_k, cudaFuncAttributeMaxDynamicSharedMemorySize,
                             (int)smem);
        flash_k<<<dim3(SEQ / 64, NH, BATCH), 256, smem>>>(q, k, v, att);
    }

    // Output projection (tensor-core tf32)
    tc_gemm<<<dim3(DIM / 128, ROWS / 128), 256>>>(att, w0T, out, ROWS, DIM, DIM);
}

// round 8
// speedup vs baseline: 3.0700x; 1.8443x over previous
#include <cuda_runtime.h>
#include <cstdint>
#include <math.h>

#define BATCH 2
#define SEQ   2048
#define DIM   2048
#define NH    16
#define NKV   4
#define HD    128
#define KVDIM (NKV * HD)      // 512
#define ROWS  (BATCH * SEQ)   // 4096

// Scratch (device globals: allocation-free per harness rules)
static __device__ float g_q[(size_t)ROWS * DIM];       // 32 MB
static __device__ float g_k[(size_t)ROWS * KVDIM];     //  8 MB
static __device__ float g_v[(size_t)ROWS * KVDIM];     //  8 MB
static __device__ float g_att[(size_t)ROWS * DIM];     // 32 MB
static __device__ float g_wqT[(size_t)DIM * DIM];      // 16 MB  [N,K] tf32-rounded
static __device__ float g_wkT[(size_t)KVDIM * DIM];    //  4 MB
static __device__ float g_wvT[(size_t)KVDIM * DIM];    //  4 MB
static __device__ float g_w0T[(size_t)DIM * DIM];      // 16 MB

__device__ __forceinline__ uint32_t f2tf32(float x) {
    uint32_t r;
    asm("cvt.rna.tf32.f32 %0, %1;" : "=r"(r) : "f"(x));
    return r;
}
__device__ __forceinline__ float fexp2(float x) {
    float y;
    asm("ex2.approx.f32 %0, %1;" : "=f"(y) : "f"(x));
    return y;
}
__device__ __forceinline__ void mma_tf32(float& c0, float& c1, float& c2, float& c3,
                                         uint32_t a0, uint32_t a1, uint32_t a2, uint32_t a3,
                                         uint32_t b0, uint32_t b1) {
    asm volatile(
        "mma.sync.aligned.m16n8k8.row.col.f32.tf32.tf32.f32 "
        "{%0,%1,%2,%3}, {%4,%5,%6,%7}, {%8,%9}, {%0,%1,%2,%3};"
        : "+f"(c0), "+f"(c1), "+f"(c2), "+f"(c3)
        : "r"(a0), "r"(a1), "r"(a2), "r"(a3), "r"(b0), "r"(b1));
}

// ---------------------------------------------------------------------------
// Transpose + tf32(RNE) round: W[K,N] row-major -> WT[N,K] row-major
// ---------------------------------------------------------------------------
__global__ void transpose_tf32_k(const float* __restrict__ W,
                                 float* __restrict__ WT, int K, int N)
{
    __shared__ float t[32][33];
    int x = blockIdx.x * 32 + threadIdx.x;  // N
    int y = blockIdx.y * 32 + threadIdx.y;  // K
    #pragma unroll
    for (int i = 0; i < 32; i += 8)
        t[threadIdx.y + i][threadIdx.x] = W[(size_t)(y + i) * N + x];
    __syncthreads();
    int xo = blockIdx.y * 32 + threadIdx.x;  // K
    int yo = blockIdx.x * 32 + threadIdx.y;  // N
    uint32_t* O = (uint32_t*)WT;
    #pragma unroll
    for (int i = 0; i < 32; i += 8)
        O[(size_t)(yo + i) * K + xo] = f2tf32(t[threadIdx.x][threadIdx.y + i]);
}

// ---------------------------------------------------------------------------
// Tensor-core tf32 GEMM via mma.sync:  C[M,N] = A[M,K] @ BT[N,K]^T
// (unchanged from R6 passing version)
// ---------------------------------------------------------------------------
__global__ __launch_bounds__(256, 2) void tc_gemm(const float* __restrict__ A,
                                                  const float* __restrict__ BT,
                                                  float* __restrict__ C,
                                                  int M, int N, int K)
{
    __shared__ float As[2][128][20];
    __shared__ float Bs[2][128][20];

    const int tid = threadIdx.x;
    const int wid = tid >> 5;
    const int lane = tid & 31;
    const int g  = lane >> 2;
    const int t4 = lane & 3;
    const int wm = (wid >> 2) * 64;
    const int wn = (wid & 3) * 32;
    const int bm = blockIdx.y * 128;
    const int bn = blockIdx.x * 128;

    const int lr = tid >> 2;
    const int lc = (tid & 3) * 4;

    float c[4][4][4];
    #pragma unroll
    for (int mt = 0; mt < 4; mt++)
        #pragma unroll
        for (int nt = 0; nt < 4; nt++)
            #pragma unroll
            for (int r = 0; r < 4; r++) c[mt][nt][r] = 0.0f;

    const int nk = K >> 4;

    {
        const float* Ap = A + (size_t)bm * K;
        const float* Bp = BT + (size_t)bn * K;
        #pragma unroll
        for (int h = 0; h < 2; h++) {
            int r = lr + 64 * h;
            float4 av = *(const float4*)(Ap + (size_t)r * K + lc);
            uint4 au;
            au.x = f2tf32(av.x); au.y = f2tf32(av.y);
            au.z = f2tf32(av.z); au.w = f2tf32(av.w);
            *(uint4*)&As[0][r][lc] = au;
            *(float4*)&Bs[0][r][lc] = *(const float4*)(Bp + (size_t)r * K + lc);
        }
    }
    __syncthreads();

    for (int tIt = 0; tIt < nk; ++tIt) {
        const int cur = tIt & 1;
        const int nxt = cur ^ 1;
        const bool more = (tIt + 1) < nk;

        float4 an[2], bnx[2];
        if (more) {
            const int k0 = (tIt + 1) << 4;
            const float* Ap = A + (size_t)bm * K + k0;
            const float* Bp = BT + (size_t)bn * K + k0;
            #pragma unroll
            for (int h = 0; h < 2; h++) {
                int r = lr + 64 * h;
                an[h]  = *(const float4*)(Ap + (size_t)r * K + lc);
                bnx[h] = *(const float4*)(Bp + (size_t)r * K + lc);
            }
        }

        #pragma unroll
        for (int kk = 0; kk < 16; kk += 8) {
            uint32_t af[4][4];
            #pragma unroll
            for (int mt = 0; mt < 4; mt++) {
                int r0 = wm + mt * 16 + g;
                af[mt][0] = __float_as_uint(As[cur][r0][kk + t4]);
                af[mt][1] = __float_as_uint(As[cur][r0 + 8][kk + t4]);
                af[mt][2] = __float_as_uint(As[cur][r0][kk + t4 + 4]);
                af[mt][3] = __float_as_uint(As[cur][r0 + 8][kk + t4 + 4]);
            }
            uint32_t bf[4][2];
            #pragma unroll
            for (int nt = 0; nt < 4; nt++) {
                int n0 = wn + nt * 8 + g;
                bf[nt][0] = __float_as_uint(Bs[cur][n0][kk + t4]);
                bf[nt][1] = __float_as_uint(Bs[cur][n0][kk + t4 + 4]);
            }
            #pragma unroll
            for (int mt = 0; mt < 4; mt++)
                #pragma unroll
                for (int nt = 0; nt < 4; nt++)
                    mma_tf32(c[mt][nt][0], c[mt][nt][1], c[mt][nt][2], c[mt][nt][3],
                             af[mt][0], af[mt][1], af[mt][2], af[mt][3],
                             bf[nt][0], bf[nt][1]);
        }

        if (more) {
            #pragma unroll
            for (int h = 0; h < 2; h++) {
                int r = lr + 64 * h;
                uint4 au;
                au.x = f2tf32(an[h].x); au.y = f2tf32(an[h].y);
                au.z = f2tf32(an[h].z); au.w = f2tf32(an[h].w);
                *(uint4*)&As[nxt][r][lc] = au;
                *(float4*)&Bs[nxt][r][lc] = bnx[h];
            }
        }
        __syncthreads();
    }

    #pragma unroll
    for (int mt = 0; mt < 4; mt++) {
        int row = bm + wm + mt * 16 + g;
        #pragma unroll
        for (int nt = 0; nt < 4; nt++) {
            int col = bn + wn + nt * 8 + t4 * 2;
            float2 v0 = make_float2(c[mt][nt][0], c[mt][nt][1]);
            float2 v1 = make_float2(c[mt][nt][2], c[mt][nt][3]);
            *(float2*)(C + (size_t)row * N + col) = v0;
            *(float2*)(C + (size_t)(row + 8) * N + col) = v1;
        }
    }
}

// ---------------------------------------------------------------------------
// RoPE (unchanged)
// ---------------------------------------------------------------------------
__global__ void rope_k(float* __restrict__ d, int rowlen, int npairs)
{
    int idx = blockIdx.x * blockDim.x + threadIdx.x;
    if (idx >= npairs) return;
    const int pr  = rowlen >> 1;
    const int row = idx / pr;
    const int col = (idx - row * pr) * 2;
    const int p   = (col & (HD - 1)) >> 1;
    const int s   = row & (SEQ - 1);

    float freq = exp2f(-(float)p * 0.2076205059304640f);
    double angd = (double)s * (double)freq;
    double kturns = floor(angd * 0.15915494309189535);
    float ang = (float)(angd - kturns * 6.283185307179586);
    float sn, cs;
    sincosf(ang, &sn, &cs);

    float* ptr = d + (size_t)row * rowlen + col;
    float re = ptr[0];
    float im = ptr[1];
    ptr[0] = re * sn - im * cs;
    ptr[1] = re * cs + im * sn;
}

// ---------------------------------------------------------------------------
// Tensor-core flash attention (tf32 mma.sync).
// BR=128, BC=64, HD=128. 256 threads = 8 warps; warp w owns Q rows [w*16, w*16+16).
// Q fragments in registers (tf32). K/V staged per tile into padded smem.
// P round-trips through smem (C-fragment -> A-fragment layout change).
// Softmax in log2 domain (log2e folded into Q scale); li sums tf32-rounded P.
// Smem pads: Ks 132, Vs 136, Ps 68 -> all fragment LDS patterns conflict-free.
// ---------------------------------------------------------------------------
#define KS_PAD 132
#define VS_PAD 136
#define PS_PAD 68
#define FLTC_SMEM ((64 * KS_PAD + 64 * VS_PAD + 128 * PS_PAD) * 4)  // 103424 B

__global__ __launch_bounds__(256, 1) void flash_tc(const float* __restrict__ Qg,
                                                   const float* __restrict__ Kg,
                                                   const float* __restrict__ Vg,
                                                   float* __restrict__ Og)
{
    extern __shared__ float smf[];
    float* Ks = smf;                      // [64][132]
    float* Vs = Ks + 64 * KS_PAD;         // [64][136]
    float* Ps = Vs + 64 * VS_PAD;         // [128][68] (also Q staging)

    const int tid = threadIdx.x;
    const int lane = tid & 31;
    const int wid = tid >> 5;
    const int g  = lane >> 2;
    const int t4 = lane & 3;
    const int wm = wid * 16;

    const int b  = blockIdx.z;
    const int h  = blockIdx.y;
    const int q0 = blockIdx.x * 128;
    const int kvh = h >> 2;
    // 1/sqrt(128) * log2(e): softmax done base-2
    const float qscale = 0.08838834764831845f * 1.4426950408889634f;

    const float* Qb = Qg + (size_t)b * SEQ * DIM + h * HD;
    const float* Kb = Kg + (size_t)b * SEQ * KVDIM + kvh * HD;
    const float* Vb = Vg + (size_t)b * SEQ * KVDIM + kvh * HD;

    // ---- Stage Q into registers as tf32 A-fragments (two 64-col phases) ----
    uint32_t qf[16][4];
    #pragma unroll
    for (int ph = 0; ph < 2; ph++) {
        const int d0 = ph * 64;
        #pragma unroll
        for (int i = 0; i < 8; i++) {
            int idx = tid + 256 * i;          // 0..2047
            int r = idx >> 4;                 // 0..127
            int c4 = (idx & 15) << 2;         // 0..60
            float4 v = *(const float4*)(Qb + (size_t)(q0 + r) * DIM + d0 + c4);
            uint4 u;
            u.x = f2tf32(v.x * qscale); u.y = f2tf32(v.y * qscale);
            u.z = f2tf32(v.z * qscale); u.w = f2tf32(v.w * qscale);
            *(uint4*)&Ps[r * PS_PAD + c4] = u;
        }
        __syncthreads();
        #pragma unroll
        for (int j = 0; j < 8; j++) {
            int ks = ph * 8 + j;
            qf[ks][0] = __float_as_uint(Ps[(wm + g) * PS_PAD + j * 8 + t4]);
            qf[ks][1] = __float_as_uint(Ps[(wm + g + 8) * PS_PAD + j * 8 + t4]);
            qf[ks][2] = __float_as_uint(Ps[(wm + g) * PS_PAD + j * 8 + t4 + 4]);
            qf[ks][3] = __float_as_uint(Ps[(wm + g + 8) * PS_PAD + j * 8 + t4 + 4]);
        }
        __syncthreads();
    }

    float o[16][4];
    #pragma unroll
    for (int nt = 0; nt < 16; nt++)
        #pragma unroll
        for (int r = 0; r < 4; r++) o[nt][r] = 0.0f;
    float mi0 = -1e30f, mi1 = -1e30f, li0 = 0.0f, li1 = 0.0f;

    const int ig0 = q0 + wm + g;
    const int ig1 = ig0 + 8;
    const int ntiles = (q0 >> 6) + 2;

    for (int kt = 0; kt < ntiles; ++kt) {
        const int j0 = kt * 64;

        // ---- Stage K,V tiles (tf32-rounded) ----
        #pragma unroll
        for (int i = 0; i < 8; i++) {
            int idx = tid + 256 * i;          // 0..2047
            int r = idx >> 5;                 // 0..63
            int c4 = (idx & 31) << 2;         // 0..124
            float4 kv = *(const float4*)(Kb + (size_t)(j0 + r) * KVDIM + c4);
            uint4 ku;
            ku.x = f2tf32(kv.x); ku.y = f2tf32(kv.y);
            ku.z = f2tf32(kv.z); ku.w = f2tf32(kv.w);
            *(uint4*)&Ks[r * KS_PAD + c4] = ku;
            float4 vv = *(const float4*)(Vb + (size_t)(j0 + r) * KVDIM + c4);
            uint4 vu;
            vu.x = f2tf32(vv.x); vu.y = f2tf32(vv.y);
            vu.z = f2tf32(vv.z); vu.w = f2tf32(vv.w);
            *(uint4*)&Vs[r * VS_PAD + c4] = vu;
        }
        __syncthreads();

        // ---- S = Q @ K^T ----
        float sf[8][4];
        #pragma unroll
        for (int nt = 0; nt < 8; nt++)
            #pragma unroll
            for (int r = 0; r < 4; r++) sf[nt][r] = 0.0f;

        #pragma unroll
        for (int ks = 0; ks < 16; ks++) {
            #pragma unroll
            for (int nt = 0; nt < 8; nt++) {
                uint32_t b0 = __float_as_uint(Ks[(nt * 8 + g) * KS_PAD + ks * 8 + t4]);
                uint32_t b1 = __float_as_uint(Ks[(nt * 8 + g) * KS_PAD + ks * 8 + t4 + 4]);
                mma_tf32(sf[nt][0], sf[nt][1], sf[nt][2], sf[nt][3],
                         qf[ks][0], qf[ks][1], qf[ks][2], qf[ks][3], b0, b1);
            }
        }

        // ---- Causal mask (only the last two tiles can intersect diagonal) ----
        if (kt >= ntiles - 2) {
            #pragma unroll
            for (int nt = 0; nt < 8; nt++) {
                int jg = j0 + nt * 8 + 2 * t4;
                if (jg     > ig0) sf[nt][0] = -1e30f;
                if (jg + 1 > ig0) sf[nt][1] = -1e30f;
                if (jg     > ig1) sf[nt][2] = -1e30f;
                if (jg + 1 > ig1) sf[nt][3] = -1e30f;
            }
        }

        // ---- Online softmax (base 2), rows g and g+8 ----
        float m0 = -1e30f, m1 = -1e30f;
        #pragma unroll
        for (int nt = 0; nt < 8; nt++) {
            m0 = fmaxf(m0, fmaxf(sf[nt][0], sf[nt][1]));
            m1 = fmaxf(m1, fmaxf(sf[nt][2], sf[nt][3]));
        }
        m0 = fmaxf(m0, __shfl_xor_sync(0xffffffffu, m0, 1));
        m0 = fmaxf(m0, __shfl_xor_sync(0xffffffffu, m0, 2));
        m1 = fmaxf(m1, __shfl_xor_sync(0xffffffffu, m1, 1));
        m1 = fmaxf(m1, __shfl_xor_sync(0xffffffffu, m1, 2));

        float mn0 = fmaxf(mi0, m0);
        float mn1 = fmaxf(mi1, m1);
        float alpha0 = fexp2(mi0 - mn0);
        float alpha1 = fexp2(mi1 - mn1);
        mi0 = mn0; mi1 = mn1;

        float l0 = 0.0f, l1 = 0.0f;
        #pragma unroll
        for (int nt = 0; nt < 8; nt++) {
            float p0 = __uint_as_float(f2tf32(fexp2(sf[nt][0] - mn0)));
            float p1 = __uint_as_float(f2tf32(fexp2(sf[nt][1] - mn0)));
            float p2 = __uint_as_float(f2tf32(fexp2(sf[nt][2] - mn1)));
            float p3 = __uint_as_float(f2tf32(fexp2(sf[nt][3] - mn1)));
            l0 += p0 + p1;
            l1 += p2 + p3;
            *(float2*)&Ps[(wm + g) * PS_PAD + nt * 8 + 2 * t4]     = make_float2(p0, p1);
            *(float2*)&Ps[(wm + g + 8) * PS_PAD + nt * 8 + 2 * t4] = make_float2(p2, p3);
        }
        l0 += __shfl_xor_sync(0xffffffffu, l0, 1);
        l0 += __shfl_xor_sync(0xffffffffu, l0, 2);
        l1 += __shfl_xor_sync(0xffffffffu, l1, 1);
        l1 += __shfl_xor_sync(0xffffffffu, l1, 2);
        li0 = li0 * alpha0 + l0;
        li1 = li1 * alpha1 + l1;

        #pragma unroll
        for (int nt = 0; nt < 16; nt++) {
            o[nt][0] *= alpha0; o[nt][1] *= alpha0;
            o[nt][2] *= alpha1; o[nt][3] *= alpha1;
        }
        __syncwarp();   // P rows are warp-private: warp-level RAW only

        // ---- O += P @ V ----
        #pragma unroll
        for (int ks2 = 0; ks2 < 8; ks2++) {
            uint32_t a0 = __float_as_uint(Ps[(wm + g) * PS_PAD + ks2 * 8 + t4]);
            uint32_t a1 = __float_as_uint(Ps[(wm + g + 8) * PS_PAD + ks2 * 8 + t4]);
            uint32_t a2 = __float_as_uint(Ps[(wm + g) * PS_PAD + ks2 * 8 + t4 + 4]);
            uint32_t a3 = __float_as_uint(Ps[(wm + g + 8) * PS_PAD + ks2 * 8 + t4 + 4]);
            #pragma unroll
            for (int nt = 0; nt < 16; nt++) {
                uint32_t b0 = __float_as_uint(Vs[(ks2 * 8 + t4) * VS_PAD + nt * 8 + g]);
                uint32_t b1 = __float_as_uint(Vs[(ks2 * 8 + t4 + 4) * VS_PAD + nt * 8 + g]);
                mma_tf32(o[nt][0], o[nt][1], o[nt][2], o[nt][3],
                         a0, a1, a2, a3, b0, b1);
            }
        }
        __syncthreads();  // protect Ks/Vs before next tile's staging
    }

    // ---- Epilogue: normalize and store ----
    const float inv0 = 1.0f / li0;
    const float inv1 = 1.0f / li1;
    float* Ob = Og + (size_t)(b * SEQ + q0) * DIM + h * HD;
    #pragma unroll
    for (int nt = 0; nt < 16; nt++) {
        int col = nt * 8 + 2 * t4;
        *(float2*)(Ob + (size_t)(wm + g) * DIM + col) =
            make_float2(o[nt][0] * inv0, o[nt][1] * inv0);
        *(float2*)(Ob + (size_t)(wm + g + 8) * DIM + col) =
            make_float2(o[nt][2] * inv1, o[nt][3] * inv1);
    }
}

// ---------------------------------------------------------------------------
extern "C" void kernel_launch(void* const* d_in, const int* in_sizes, int n_in,
                              void* d_out, int out_size)
{
    const float* x  = (const float*)d_in[0];
    const float* wq = (const float*)d_in[1];
    const float* wk = (const float*)d_in[2];
    const float* wv = (const float*)d_in[3];
    const float* w0 = (const float*)d_in[4];
    float* out = (float*)d_out;

    float *q, *k, *v, *att, *wqT, *wkT, *wvT, *w0T;
    cudaGetSymbolAddress((void**)&q,   g_q);
    cudaGetSymbolAddress((void**)&k,   g_k);
    cudaGetSymbolAddress((void**)&v,   g_v);
    cudaGetSymbolAddress((void**)&att, g_att);
    cudaGetSymbolAddress((void**)&wqT, g_wqT);
    cudaGetSymbolAddress((void**)&wkT, g_wkT);
    cudaGetSymbolAddress((void**)&wvT, g_wvT);
    cudaGetSymbolAddress((void**)&w0T, g_w0T);

    // Transpose + tf32-round all weights
    {
        dim3 blk(32, 8);
        transpose_tf32_k<<<dim3(DIM / 32,   DIM / 32), blk>>>(wq, wqT, DIM, DIM);
        transpose_tf32_k<<<dim3(KVDIM / 32, DIM / 32), blk>>>(wk, wkT, DIM, KVDIM);
        transpose_tf32_k<<<dim3(KVDIM / 32, DIM / 32), blk>>>(wv, wvT, DIM, KVDIM);
        transpose_tf32_k<<<dim3(DIM / 32,   DIM / 32), blk>>>(w0, w0T, DIM, DIM);
    }

    // QKV projections (tensor-core tf32)
    tc_gemm<<<dim3(DIM / 128,   ROWS / 128), 256>>>(x, wqT, q, ROWS, DIM, DIM);
    tc_gemm<<<dim3(KVDIM / 128, ROWS / 128), 256>>>(x, wkT, k, ROWS, KVDIM, DIM);
    tc_gemm<<<dim3(KVDIM / 128, ROWS / 128), 256>>>(x, wvT, v, ROWS, KVDIM, DIM);

    // RoPE on q and k
    {
        int npq = ROWS * DIM / 2;
        rope_k<<<(npq + 255) / 256, 256>>>(q, DIM, npq);
        int npk = ROWS * KVDIM / 2;
        rope_k<<<(npk + 255) / 256, 256>>>(k, KVDIM, npk);
    }

    // Tensor-core flash attention
    cudaFuncSetAttribute(flash_tc, cudaFuncAttributeMaxDynamicSharedMemorySize,
                         FLTC_SMEM);
    flash_tc<<<dim3(SEQ / 128, NH, BATCH), 256, FLTC_SMEM>>>(q, k, v, att);

    // Output projection (tensor-core tf32)
    tc_gemm<<<dim3(DIM / 128, ROWS / 128), 256>>>(att, w0T, out, ROWS, DIM, DIM);
}

// round 9
// speedup vs baseline: 3.3254x; 1.0832x over previous
#include <cuda_runtime.h>
#include <cstdint>
#include <math.h>

#define BATCH 2
#define SEQ   2048
#define DIM   2048
#define NH    16
#define NKV   4
#define HD    128
#define KVDIM (NKV * HD)      // 512
#define ROWS  (BATCH * SEQ)   // 4096

// Scratch (device globals: allocation-free per harness rules)
static __device__ float g_x32[(size_t)ROWS * DIM];     // 32 MB  tf32-rounded x
static __device__ float g_q[(size_t)ROWS * DIM];       // 32 MB
static __device__ float g_k[(size_t)ROWS * KVDIM];     //  8 MB
static __device__ float g_v[(size_t)ROWS * KVDIM];     //  8 MB
static __device__ float g_att[(size_t)ROWS * DIM];     // 32 MB
static __device__ float g_wqT[(size_t)DIM * DIM];      // 16 MB  [N,K] tf32-rounded
static __device__ float g_wkT[(size_t)KVDIM * DIM];    //  4 MB
static __device__ float g_wvT[(size_t)KVDIM * DIM];    //  4 MB
static __device__ float g_w0T[(size_t)DIM * DIM];      // 16 MB

__device__ __forceinline__ uint32_t f2tf32(float x) {
    uint32_t r;
    asm("cvt.rna.tf32.f32 %0, %1;" : "=r"(r) : "f"(x));
    return r;
}
__device__ __forceinline__ float fexp2(float x) {
    float y;
    asm("ex2.approx.f32 %0, %1;" : "=f"(y) : "f"(x));
    return y;
}
__device__ __forceinline__ void mma_tf32(float& c0, float& c1, float& c2, float& c3,
                                         uint32_t a0, uint32_t a1, uint32_t a2, uint32_t a3,
                                         uint32_t b0, uint32_t b1) {
    asm volatile(
        "mma.sync.aligned.m16n8k8.row.col.f32.tf32.tf32.f32 "
        "{%0,%1,%2,%3}, {%4,%5,%6,%7}, {%8,%9}, {%0,%1,%2,%3};"
        : "+f"(c0), "+f"(c1), "+f"(c2), "+f"(c3)
        : "r"(a0), "r"(a1), "r"(a2), "r"(a3), "r"(b0), "r"(b1));
}
__device__ __forceinline__ uint32_t smem_u32(const void* p) {
    uint32_t a;
    asm("{ .reg .u64 t; cvta.to.shared.u64 t, %1; cvt.u32.u64 %0, t; }"
        : "=r"(a) : "l"(p));
    return a;
}
__device__ __forceinline__ void cp_async16(uint32_t dst, const void* src) {
    asm volatile("cp.async.ca.shared.global [%0], [%1], 16;"
                 :: "r"(dst), "l"(src) : "memory");
}
#define CP_COMMIT() asm volatile("cp.async.commit_group;" ::: "memory")
#define CP_WAIT(n)  asm volatile("cp.async.wait_group %0;" :: "n"(n) : "memory")

// ---------------------------------------------------------------------------
// Elementwise tf32(RNE) round (out-of-place or in-place)
// ---------------------------------------------------------------------------
__global__ void round_tf32_k(const float* __restrict__ in,
                             float* __restrict__ outp, int n4)
{
    int i = blockIdx.x * blockDim.x + threadIdx.x;
    if (i >= n4) return;
    float4 v = ((const float4*)in)[i];
    uint4 u;
    u.x = f2tf32(v.x); u.y = f2tf32(v.y);
    u.z = f2tf32(v.z); u.w = f2tf32(v.w);
    ((uint4*)outp)[i] = u;
}

// ---------------------------------------------------------------------------
// Transpose + tf32(RNE) round: W[K,N] row-major -> WT[N,K] row-major
// ---------------------------------------------------------------------------
__global__ void transpose_tf32_k(const float* __restrict__ W,
                                 float* __restrict__ WT, int K, int N)
{
    __shared__ float t[32][33];
    int x = blockIdx.x * 32 + threadIdx.x;  // N
    int y = blockIdx.y * 32 + threadIdx.y;  // K
    #pragma unroll
    for (int i = 0; i < 32; i += 8)
        t[threadIdx.y + i][threadIdx.x] = W[(size_t)(y + i) * N + x];
    __syncthreads();
    int xo = blockIdx.y * 32 + threadIdx.x;  // K
    int yo = blockIdx.x * 32 + threadIdx.y;  // N
    uint32_t* O = (uint32_t*)WT;
    #pragma unroll
    for (int i = 0; i < 32; i += 8)
        O[(size_t)(yo + i) * K + xo] = f2tf32(t[threadIdx.x][threadIdx.y + i]);
}

// ---------------------------------------------------------------------------
// Tensor-core tf32 GEMM, 4-stage cp.async pipeline.
// C[M,N] = A[M,K] @ BT[N,K]^T ; A and BT both pre-rounded to tf32.
// CTA tile 128x128, BK=16, 256 threads (8 warps, 2x4), warp tile 64x32.
// Dynamic smem: 4 stages x (A[128][20] + B[128][20]) = 81920 B.
// Requires M%128==0, N%128==0, K%16==0, K/16 >= 3.
// ---------------------------------------------------------------------------
#define GSTAGE_FLOATS (2 * 128 * 20)                 // 5120 floats per stage
#define GEMM2_SMEM    (4 * GSTAGE_FLOATS * 4)        // 81920 B

__global__ __launch_bounds__(256, 2) void tc_gemm2(const float* __restrict__ A,
                                                   const float* __restrict__ BT,
                                                   float* __restrict__ C,
                                                   int M, int N, int K)
{
    extern __shared__ float smg[];
    const uint32_t smb = smem_u32(smg);

    const int tid = threadIdx.x;
    const int wid = tid >> 5;
    const int lane = tid & 31;
    const int g  = lane >> 2;
    const int t4 = lane & 3;
    const int wm = (wid >> 2) * 64;
    const int wn = (wid & 3) * 32;
    const int bm = blockIdx.y * 128;
    const int bn = blockIdx.x * 128;

    const int lr = tid >> 2;          // row 0..63 (and +64)
    const int lc = (tid & 3) * 4;     // k-col floats 0/4/8/12

    float c[4][4][4];
    #pragma unroll
    for (int mt = 0; mt < 4; mt++)
        #pragma unroll
        for (int nt = 0; nt < 4; nt++)
            #pragma unroll
            for (int r = 0; r < 4; r++) c[mt][nt][r] = 0.0f;

    const int nk = K >> 4;

    // Per-stage byte offsets for this thread's 4 copies
    const uint32_t aOff0 = ((lr)      * 20 + lc) * 4;
    const uint32_t aOff1 = ((lr + 64) * 20 + lc) * 4;
    const uint32_t bBase = 128 * 20 * 4;            // B after A within stage
    const uint32_t stageBytes = GSTAGE_FLOATS * 4;  // 20480

    // Prologue: issue stages 0..2
    #pragma unroll
    for (int s = 0; s < 3; s++) {
        const int k0 = s << 4;
        const float* Ap = A + (size_t)bm * K + k0;
        const float* Bp = BT + (size_t)bn * K + k0;
        uint32_t sb = smb + s * stageBytes;
        cp_async16(sb + aOff0, Ap + (size_t)lr * K + lc);
        cp_async16(sb + aOff1, Ap + (size_t)(lr + 64) * K + lc);
        cp_async16(sb + bBase + aOff0, Bp + (size_t)lr * K + lc);
        cp_async16(sb + bBase + aOff1, Bp + (size_t)(lr + 64) * K + lc);
        CP_COMMIT();
    }

    for (int t = 0; t < nk; ++t) {
        CP_WAIT(2);           // stage t landed
        __syncthreads();      // visibility + all warps done with stage (t+3)%4

        const float* As = smg + (t & 3) * GSTAGE_FLOATS;
        const float* Bs = As + 128 * 20;

        #pragma unroll
        for (int kk = 0; kk < 16; kk += 8) {
            uint32_t af[4][4];
            #pragma unroll
            for (int mt = 0; mt < 4; mt++) {
                int r0 = wm + mt * 16 + g;
                af[mt][0] = __float_as_uint(As[r0 * 20 + kk + t4]);
                af[mt][1] = __float_as_uint(As[(r0 + 8) * 20 + kk + t4]);
                af[mt][2] = __float_as_uint(As[r0 * 20 + kk + t4 + 4]);
                af[mt][3] = __float_as_uint(As[(r0 + 8) * 20 + kk + t4 + 4]);
            }
            uint32_t bf[4][2];
            #pragma unroll
            for (int nt = 0; nt < 4; nt++) {
                int n0 = wn + nt * 8 + g;
                bf[nt][0] = __float_as_uint(Bs[n0 * 20 + kk + t4]);
                bf[nt][1] = __float_as_uint(Bs[n0 * 20 + kk + t4 + 4]);
            }
            #pragma unroll
            for (int mt = 0; mt < 4; mt++)
                #pragma unroll
                for (int nt = 0; nt < 4; nt++)
                    mma_tf32(c[mt][nt][0], c[mt][nt][1], c[mt][nt][2], c[mt][nt][3],
                             af[mt][0], af[mt][1], af[mt][2], af[mt][3],
                             bf[nt][0], bf[nt][1]);
        }

        // Issue stage t+3 (overwrites buffer last read at iteration t-1)
        const int tn = t + 3;
        if (tn < nk) {
            const int k0 = tn << 4;
            const float* Ap = A + (size_t)bm * K + k0;
            const float* Bp = BT + (size_t)bn * K + k0;
            uint32_t sb = smb + (tn & 3) * stageBytes;
            cp_async16(sb + aOff0, Ap + (size_t)lr * K + lc);
            cp_async16(sb + aOff1, Ap + (size_t)(lr + 64) * K + lc);
            cp_async16(sb + bBase + aOff0, Bp + (size_t)lr * K + lc);
            cp_async16(sb + bBase + aOff1, Bp + (size_t)(lr + 64) * K + lc);
        }
        CP_COMMIT();
    }

    #pragma unroll
    for (int mt = 0; mt < 4; mt++) {
        int row = bm + wm + mt * 16 + g;
        #pragma unroll
        for (int nt = 0; nt < 4; nt++) {
            int col = bn + wn + nt * 8 + t4 * 2;
            float2 v0 = make_float2(c[mt][nt][0], c[mt][nt][1]);
            float2 v1 = make_float2(c[mt][nt][2], c[mt][nt][3]);
            *(float2*)(C + (size_t)row * N + col) = v0;
            *(float2*)(C + (size_t)(row + 8) * N + col) = v1;
        }
    }
}

// ---------------------------------------------------------------------------
// RoPE, replicating the reference's swapped-argument call; output scaled by
// oscale and RNE-rounded to tf32 (pre-conditioning for the MMA consumers).
// ---------------------------------------------------------------------------
__global__ void rope_k(float* __restrict__ d, int rowlen, int npairs, float oscale)
{
    int idx = blockIdx.x * blockDim.x + threadIdx.x;
    if (idx >= npairs) return;
    const int pr  = rowlen >> 1;
    const int row = idx / pr;
    const int col = (idx - row * pr) * 2;
    const int p   = (col & (HD - 1)) >> 1;
    const int s   = row & (SEQ - 1);

    float freq = exp2f(-(float)p * 0.2076205059304640f);
    double angd = (double)s * (double)freq;
    double kturns = floor(angd * 0.15915494309189535);
    float ang = (float)(angd - kturns * 6.283185307179586);
    float sn, cs;
    sincosf(ang, &sn, &cs);

    float* ptr = d + (size_t)row * rowlen + col;
    float re = ptr[0];
    float im = ptr[1];
    uint32_t* up = (uint32_t*)ptr;
    up[0] = f2tf32((re * sn - im * cs) * oscale);
    up[1] = f2tf32((re * cs + im * sn) * oscale);
}

// ---------------------------------------------------------------------------
// Tensor-core flash attention (tf32 mma.sync). Inputs pre-rounded (q also
// pre-scaled by 1/sqrt(HD)*log2e). Epilogue rounds att for the w0 GEMM.
// ---------------------------------------------------------------------------
#define KS_PAD 132
#define VS_PAD 136
#define PS_PAD 68
#define FLTC_SMEM ((64 * KS_PAD + 64 * VS_PAD + 128 * PS_PAD) * 4)  // 103424 B

__global__ __launch_bounds__(256, 1) void flash_tc(const float* __restrict__ Qg,
                                                   const float* __restrict__ Kg,
                                                   const float* __restrict__ Vg,
                                                   float* __restrict__ Og)
{
    extern __shared__ float smf[];
    float* Ks = smf;                      // [64][132]
    float* Vs = Ks + 64 * KS_PAD;         // [64][136]
    float* Ps = Vs + 64 * VS_PAD;         // [128][68] (also Q staging)

    const int tid = threadIdx.x;
    const int lane = tid & 31;
    const int wid = tid >> 5;
    const int g  = lane >> 2;
    const int t4 = lane & 3;
    const int wm = wid * 16;

    const int b  = blockIdx.z;
    const int h  = blockIdx.y;
    const int q0 = blockIdx.x * 128;
    const int kvh = h >> 2;

    const float* Qb = Qg + (size_t)b * SEQ * DIM + h * HD;
    const float* Kb = Kg + (size_t)b * SEQ * KVDIM + kvh * HD;
    const float* Vb = Vg + (size_t)b * SEQ * KVDIM + kvh * HD;

    // ---- Stage Q (pre-rounded, pre-scaled) into register A-fragments ----
    uint32_t qf[16][4];
    #pragma unroll
    for (int ph = 0; ph < 2; ph++) {
        const int d0 = ph * 64;
        #pragma unroll
        for (int i = 0; i < 8; i++) {
            int idx = tid + 256 * i;
            int r = idx >> 4;
            int c4 = (idx & 15) << 2;
            *(float4*)&Ps[r * PS_PAD + c4] =
                *(const float4*)(Qb + (size_t)(q0 + r) * DIM + d0 + c4);
        }
        __syncthreads();
        #pragma unroll
        for (int j = 0; j < 8; j++) {
            int ks = ph * 8 + j;
            qf[ks][0] = __float_as_uint(Ps[(wm + g) * PS_PAD + j * 8 + t4]);
            qf[ks][1] = __float_as_uint(Ps[(wm + g + 8) * PS_PAD + j * 8 + t4]);
            qf[ks][2] = __float_as_uint(Ps[(wm + g) * PS_PAD + j * 8 + t4 + 4]);
            qf[ks][3] = __float_as_uint(Ps[(wm + g + 8) * PS_PAD + j * 8 + t4 + 4]);
        }
        __syncthreads();
    }

    float o[16][4];
    #pragma unroll
    for (int nt = 0; nt < 16; nt++)
        #pragma unroll
        for (int r = 0; r < 4; r++) o[nt][r] = 0.0f;
    float mi0 = -1e30f, mi1 = -1e30f, li0 = 0.0f, li1 = 0.0f;

    const int ig0 = q0 + wm + g;
    const int ig1 = ig0 + 8;
    const int ntiles = (q0 >> 6) + 2;

    for (int kt = 0; kt < ntiles; ++kt) {
        const int j0 = kt * 64;

        // ---- Stage K,V (pre-rounded): pure copy ----
        #pragma unroll
        for (int i = 0; i < 8; i++) {
            int idx = tid + 256 * i;
            int r = idx >> 5;
            int c4 = (idx & 31) << 2;
            *(float4*)&Ks[r * KS_PAD + c4] =
                *(const float4*)(Kb + (size_t)(j0 + r) * KVDIM + c4);
            *(float4*)&Vs[r * VS_PAD + c4] =
                *(const float4*)(Vb + (size_t)(j0 + r) * KVDIM + c4);
        }
        __syncthreads();

        // ---- S = Q @ K^T ----
        float sf[8][4];
        #pragma unroll
        for (int nt = 0; nt < 8; nt++)
            #pragma unroll
            for (int r = 0; r < 4; r++) sf[nt][r] = 0.0f;

        #pragma unroll
        for (int ks = 0; ks < 16; ks++) {
            #pragma unroll
            for (int nt = 0; nt < 8; nt++) {
                uint32_t b0 = __float_as_uint(Ks[(nt * 8 + g) * KS_PAD + ks * 8 + t4]);
                uint32_t b1 = __float_as_uint(Ks[(nt * 8 + g) * KS_PAD + ks * 8 + t4 + 4]);
                mma_tf32(sf[nt][0], sf[nt][1], sf[nt][2], sf[nt][3],
                         qf[ks][0], qf[ks][1], qf[ks][2], qf[ks][3], b0, b1);
            }
        }

        // ---- Causal mask ----
        if (kt >= ntiles - 2) {
            #pragma unroll
            for (int nt = 0; nt < 8; nt++) {
                int jg = j0 + nt * 8 + 2 * t4;
                if (jg     > ig0) sf[nt][0] = -1e30f;
                if (jg + 1 > ig0) sf[nt][1] = -1e30f;
                if (jg     > ig1) sf[nt][2] = -1e30f;
                if (jg + 1 > ig1) sf[nt][3] = -1e30f;
            }
        }

        // ---- Online softmax (base 2) ----
        float m0 = -1e30f, m1 = -1e30f;
        #pragma unroll
        for (int nt = 0; nt < 8; nt++) {
            m0 = fmaxf(m0, fmaxf(sf[nt][0], sf[nt][1]));
            m1 = fmaxf(m1, fmaxf(sf[nt][2], sf[nt][3]));
        }
        m0 = fmaxf(m0, __shfl_xor_sync(0xffffffffu, m0, 1));
        m0 = fmaxf(m0, __shfl_xor_sync(0xffffffffu, m0, 2));
        m1 = fmaxf(m1, __shfl_xor_sync(0xffffffffu, m1, 1));
        m1 = fmaxf(m1, __shfl_xor_sync(0xffffffffu, m1, 2));

        float mn0 = fmaxf(mi0, m0);
        float mn1 = fmaxf(mi1, m1);
        float alpha0 = fexp2(mi0 - mn0);
        float alpha1 = fexp2(mi1 - mn1);
        mi0 = mn0; mi1 = mn1;

        float l0 = 0.0f, l1 = 0.0f;
        #pragma unroll
        for (int nt = 0; nt < 8; nt++) {
            float p0 = __uint_as_float(f2tf32(fexp2(sf[nt][0] - mn0)));
            float p1 = __uint_as_float(f2tf32(fexp2(sf[nt][1] - mn0)));
            float p2 = __uint_as_float(f2tf32(fexp2(sf[nt][2] - mn1)));
            float p3 = __uint_as_float(f2tf32(fexp2(sf[nt][3] - mn1)));
            l0 += p0 + p1;
            l1 += p2 + p3;
            *(float2*)&Ps[(wm + g) * PS_PAD + nt * 8 + 2 * t4]     = make_float2(p0, p1);
            *(float2*)&Ps[(wm + g + 8) * PS_PAD + nt * 8 + 2 * t4] = make_float2(p2, p3);
        }
        l0 += __shfl_xor_sync(0xffffffffu, l0, 1);
        l0 += __shfl_xor_sync(0xffffffffu, l0, 2);
        l1 += __shfl_xor_sync(0xffffffffu, l1, 1);
        l1 += __shfl_xor_sync(0xffffffffu, l1, 2);
        li0 = li0 * alpha0 + l0;
        li1 = li1 * alpha1 + l1;

        #pragma unroll
        for (int nt = 0; nt < 16; nt++) {
            o[nt][0] *= alpha0; o[nt][1] *= alpha0;
            o[nt][2] *= alpha1; o[nt][3] *= alpha1;
        }
        __syncwarp();   // P rows are warp-private

        // ---- O += P @ V ----
        #pragma unroll
        for (int ks2 = 0; ks2 < 8; ks2++) {
            uint32_t a0 = __float_as_uint(Ps[(wm + g) * PS_PAD + ks2 * 8 + t4]);
            uint32_t a1 = __float_as_uint(Ps[(wm + g + 8) * PS_PAD + ks2 * 8 + t4]);
            uint32_t a2 = __float_as_uint(Ps[(wm + g) * PS_PAD + ks2 * 8 + t4 + 4]);
            uint32_t a3 = __float_as_uint(Ps[(wm + g + 8) * PS_PAD + ks2 * 8 + t4 + 4]);
            #pragma unroll
            for (int nt = 0; nt < 16; nt++) {
                uint32_t b0 = __float_as_uint(Vs[(ks2 * 8 + t4) * VS_PAD + nt * 8 + g]);
                uint32_t b1 = __float_as_uint(Vs[(ks2 * 8 + t4 + 4) * VS_PAD + nt * 8 + g]);
                mma_tf32(o[nt][0], o[nt][1], o[nt][2], o[nt][3],
                         a0, a1, a2, a3, b0, b1);
            }
        }
        __syncthreads();
    }

    // ---- Epilogue: normalize, round to tf32 (feeds w0 GEMM), store ----
    const float inv0 = 1.0f / li0;
    const float inv1 = 1.0f / li1;
    float* Ob = Og + (size_t)(b * SEQ + q0) * DIM + h * HD;
    #pragma unroll
    for (int nt = 0; nt < 16; nt++) {
        int col = nt * 8 + 2 * t4;
        uint2 s0, s1;
        s0.x = f2tf32(o[nt][0] * inv0); s0.y = f2tf32(o[nt][1] * inv0);
        s1.x = f2tf32(o[nt][2] * inv1); s1.y = f2tf32(o[nt][3] * inv1);
        *(uint2*)(Ob + (size_t)(wm + g) * DIM + col) = s0;
        *(uint2*)(Ob + (size_t)(wm + g + 8) * DIM + col) = s1;
    }
}

// ---------------------------------------------------------------------------
extern "C" void kernel_launch(void* const* d_in, const int* in_sizes, int n_in,
                              void* d_out, int out_size)
{
    const float* x  = (const float*)d_in[0];
    const float* wq = (const float*)d_in[1];
    const float* wk = (const float*)d_in[2];
    const float* wv = (const float*)d_in[3];
    const float* w0 = (const float*)d_in[4];
    float* out = (float*)d_out;

    float *x32, *q, *k, *v, *att, *wqT, *wkT, *wvT, *w0T;
    cudaGetSymbolAddress((void**)&x32, g_x32);
    cudaGetSymbolAddress((void**)&q,   g_q);
    cudaGetSymbolAddress((void**)&k,   g_k);
    cudaGetSymbolAddress((void**)&v,   g_v);
    cudaGetSymbolAddress((void**)&att, g_att);
    cudaGetSymbolAddress((void**)&wqT, g_wqT);
    cudaGetSymbolAddress((void**)&wkT, g_wkT);
    cudaGetSymbolAddress((void**)&wvT, g_wvT);
    cudaGetSymbolAddress((void**)&w0T, g_w0T);

    // Pre-round x; transpose + round all weights
    {
        int n4 = ROWS * DIM / 4;
        round_tf32_k<<<(n4 + 255) / 256, 256>>>(x, x32, n4);
        dim3 blk(32, 8);
        transpose_tf32_k<<<dim3(DIM / 32,   DIM / 32), blk>>>(wq, wqT, DIM, DIM);
        transpose_tf32_k<<<dim3(KVDIM / 32, DIM / 32), blk>>>(wk, wkT, DIM, KVDIM);
        transpose_tf32_k<<<dim3(KVDIM / 32, DIM / 32), blk>>>(wv, wvT, DIM, KVDIM);
        transpose_tf32_k<<<dim3(DIM / 32,   DIM / 32), blk>>>(w0, w0T, DIM, DIM);
    }

    cudaFuncSetAttribute(tc_gemm2, cudaFuncAttributeMaxDynamicSharedMemorySize,
                         GEMM2_SMEM);

    // QKV projections (pipelined tf32 tensor-core GEMM)
    tc_gemm2<<<dim3(DIM / 128,   ROWS / 128), 256, GEMM2_SMEM>>>(x32, wqT, q, ROWS, DIM, DIM);
    tc_gemm2<<<dim3(KVDIM / 128, ROWS / 128), 256, GEMM2_SMEM>>>(x32, wkT, k, ROWS, KVDIM, DIM);
    tc_gemm2<<<dim3(KVDIM / 128, ROWS / 128), 256, GEMM2_SMEM>>>(x32, wvT, v, ROWS, KVDIM, DIM);

    // RoPE on q (pre-scaled by 1/sqrt(HD)*log2e) and k; round v
    {
        const float qscale = 0.08838834764831845f * 1.4426950408889634f;
        int npq = ROWS * DIM / 2;
        rope_k<<<(npq + 255) / 256, 256>>>(q, DIM, npq, qscale);
        int npk = ROWS * KVDIM / 2;
        rope_k<<<(npk + 255) / 256, 256>>>(k, KVDIM, npk, 1.0f);
        int nv4 = ROWS * KVDIM / 4;
        round_tf32_k<<<(nv4 + 255) / 256, 256>>>(v, v, nv4);
    }

    // Tensor-core flash attention
    cudaFuncSetAttribute(flash_tc, cudaFuncAttributeMaxDynamicSharedMemorySize,
                         FLTC_SMEM);
    flash_tc<<<dim3(SEQ / 128, NH, BATCH), 256, FLTC_SMEM>>>(q, k, v, att);

    // Output projection
    tc_gemm2<<<dim3(DIM / 128, ROWS / 128), 256, GEMM2_SMEM>>>(att, w0T, out, ROWS, DIM, DIM);
}

// round 10
// speedup vs baseline: 3.4420x; 1.0351x over previous
#include <cuda_runtime.h>
#include <cstdint>
#include <math.h>

#define BATCH 2
#define SEQ   2048
#define DIM   2048
#define NH    16
#define NKV   4
#define HD    128
#define KVDIM (NKV * HD)      // 512
#define ROWS  (BATCH * SEQ)   // 4096
#define QKVN  (DIM + 2 * KVDIM)   // 3072 fused projection width
#define KOFF  DIM                 // 2048: k column offset in fused buffer
#define VOFF  (DIM + KVDIM)       // 2560: v column offset

// Scratch (device globals: allocation-free per harness rules)
static __device__ float g_x32[(size_t)ROWS * DIM];       // 32 MB tf32-rounded x
static __device__ float g_qkv[(size_t)ROWS * QKVN];      // 48 MB fused q|k|v
static __device__ float g_att[(size_t)ROWS * DIM];       // 32 MB
static __device__ float g_wqkvT[(size_t)QKVN * DIM];     // 24 MB [N,K] tf32
static __device__ float g_w0T[(size_t)DIM * DIM];        // 16 MB

__device__ __forceinline__ uint32_t f2tf32(float x) {
    uint32_t r;
    asm("cvt.rna.tf32.f32 %0, %1;" : "=r"(r) : "f"(x));
    return r;
}
__device__ __forceinline__ float fexp2(float x) {
    float y;
    asm("ex2.approx.f32 %0, %1;" : "=f"(y) : "f"(x));
    return y;
}
__device__ __forceinline__ void mma_tf32(float& c0, float& c1, float& c2, float& c3,
                                         uint32_t a0, uint32_t a1, uint32_t a2, uint32_t a3,
                                         uint32_t b0, uint32_t b1) {
    asm volatile(
        "mma.sync.aligned.m16n8k8.row.col.f32.tf32.tf32.f32 "
        "{%0,%1,%2,%3}, {%4,%5,%6,%7}, {%8,%9}, {%0,%1,%2,%3};"
        : "+f"(c0), "+f"(c1), "+f"(c2), "+f"(c3)
        : "r"(a0), "r"(a1), "r"(a2), "r"(a3), "r"(b0), "r"(b1));
}
__device__ __forceinline__ uint32_t smem_u32(const void* p) {
    uint32_t a;
    asm("{ .reg .u64 t; cvta.to.shared.u64 t, %1; cvt.u32.u64 %0, t; }"
        : "=r"(a) : "l"(p));
    return a;
}
__device__ __forceinline__ void cp_async16(uint32_t dst, const void* src) {
    asm volatile("cp.async.ca.shared.global [%0], [%1], 16;"
                 :: "r"(dst), "l"(src) : "memory");
}
#define CP_COMMIT() asm volatile("cp.async.commit_group;" ::: "memory")
#define CP_WAIT(n)  asm volatile("cp.async.wait_group %0;" :: "n"(n) : "memory")

// Reference's swapped-argument RoPE: re' = re*sin - im*cos ; im' = re*cos + im*sin
__device__ __forceinline__ void rope_pair(float re, float im, int s, float freq,
                                          float oscale, uint32_t& o0, uint32_t& o1) {
    double angd = (double)s * (double)freq;
    double kturns = floor(angd * 0.15915494309189535);
    float ang = (float)(angd - kturns * 6.283185307179586);
    float sn, cs;
    sincosf(ang, &sn, &cs);
    o0 = f2tf32((re * sn - im * cs) * oscale);
    o1 = f2tf32((re * cs + im * sn) * oscale);
}

// ---------------------------------------------------------------------------
// Elementwise tf32(RNE) round
// ---------------------------------------------------------------------------
__global__ void round_tf32_k(const float* __restrict__ in,
                             float* __restrict__ outp, int n4)
{
    int i = blockIdx.x * blockDim.x + threadIdx.x;
    if (i >= n4) return;
    float4 v = ((const float4*)in)[i];
    uint4 u;
    u.x = f2tf32(v.x); u.y = f2tf32(v.y);
    u.z = f2tf32(v.z); u.w = f2tf32(v.w);
    ((uint4*)outp)[i] = u;
}

// ---------------------------------------------------------------------------
// Transpose + tf32(RNE) round: W[K,N] row-major -> WT[N,K] row-major
// (WT may point into a row-offset slice of the fused weight buffer)
// ---------------------------------------------------------------------------
__global__ void transpose_tf32_k(const float* __restrict__ W,
                                 float* __restrict__ WT, int K, int N)
{
    __shared__ float t[32][33];
    int x = blockIdx.x * 32 + threadIdx.x;  // N
    int y = blockIdx.y * 32 + threadIdx.y;  // K
    #pragma unroll
    for (int i = 0; i < 32; i += 8)
        t[threadIdx.y + i][threadIdx.x] = W[(size_t)(y + i) * N + x];
    __syncthreads();
    int xo = blockIdx.y * 32 + threadIdx.x;  // K
    int yo = blockIdx.x * 32 + threadIdx.y;  // N
    uint32_t* O = (uint32_t*)WT;
    #pragma unroll
    for (int i = 0; i < 32; i += 8)
        O[(size_t)(yo + i) * K + xo] = f2tf32(t[threadIdx.x][threadIdx.y + i]);
}

// ---------------------------------------------------------------------------
// GEMM mainloop body shared by both GEMM kernels (4-stage cp.async, BK=16).
// Leaves accumulators in c[4][4][4]; tile coords bm/bn.
// ---------------------------------------------------------------------------
#define GSTAGE_FLOATS (2 * 128 * 20)
#define GEMM2_SMEM    (4 * GSTAGE_FLOATS * 4)        // 81920 B

#define GEMM_MAINLOOP(A_, BT_, K_)                                              \
    const uint32_t aOff0 = ((lr)      * 20 + lc) * 4;                           \
    const uint32_t aOff1 = ((lr + 64) * 20 + lc) * 4;                           \
    const uint32_t bBase = 128 * 20 * 4;                                        \
    const uint32_t stageBytes = GSTAGE_FLOATS * 4;                              \
    const int nk = (K_) >> 4;                                                   \
    _Pragma("unroll")                                                           \
    for (int s = 0; s < 3; s++) {                                               \
        const int k0 = s << 4;                                                  \
        const float* Ap = (A_) + (size_t)bm * (K_) + k0;                        \
        const float* Bp = (BT_) + (size_t)bn * (K_) + k0;                       \
        uint32_t sb = smb + s * stageBytes;                                     \
        cp_async16(sb + aOff0, Ap + (size_t)lr * (K_) + lc);                    \
        cp_async16(sb + aOff1, Ap + (size_t)(lr + 64) * (K_) + lc);             \
        cp_async16(sb + bBase + aOff0, Bp + (size_t)lr * (K_) + lc);            \
        cp_async16(sb + bBase + aOff1, Bp + (size_t)(lr + 64) * (K_) + lc);     \
        CP_COMMIT();                                                            \
    }                                                                           \
    for (int t = 0; t < nk; ++t) {                                              \
        CP_WAIT(2);                                                             \
        __syncthreads();                                                        \
        const float* As = smg + (t & 3) * GSTAGE_FLOATS;                        \
        const float* Bs = As + 128 * 20;                                        \
        _Pragma("unroll")                                                       \
        for (int kk = 0; kk < 16; kk += 8) {                                    \
            uint32_t af[4][4];                                                  \
            _Pragma("unroll")                                                   \
            for (int mt = 0; mt < 4; mt++) {                                    \
                int r0 = wm + mt * 16 + g;                                      \
                af[mt][0] = __float_as_uint(As[r0 * 20 + kk + t4]);             \
                af[mt][1] = __float_as_uint(As[(r0 + 8) * 20 + kk + t4]);       \
                af[mt][2] = __float_as_uint(As[r0 * 20 + kk + t4 + 4]);         \
                af[mt][3] = __float_as_uint(As[(r0 + 8) * 20 + kk + t4 + 4]);   \
            }                                                                   \
            uint32_t bf[4][2];                                                  \
            _Pragma("unroll")                                                   \
            for (int nt = 0; nt < 4; nt++) {                                    \
                int n0 = wn + nt * 8 + g;                                       \
                bf[nt][0] = __float_as_uint(Bs[n0 * 20 + kk + t4]);             \
                bf[nt][1] = __float_as_uint(Bs[n0 * 20 + kk + t4 + 4]);         \
            }                                                                   \
            _Pragma("unroll")                                                   \
            for (int mt = 0; mt < 4; mt++)                                      \
                _Pragma("unroll")                                               \
                for (int nt = 0; nt < 4; nt++)                                  \
                    mma_tf32(c[mt][nt][0], c[mt][nt][1], c[mt][nt][2],          \
                             c[mt][nt][3], af[mt][0], af[mt][1], af[mt][2],     \
                             af[mt][3], bf[nt][0], bf[nt][1]);                  \
        }                                                                       \
        const int tn = t + 3;                                                   \
        if (tn < nk) {                                                          \
            const int k0 = tn << 4;                                             \
            const float* Ap = (A_) + (size_t)bm * (K_) + k0;                    \
            const float* Bp = (BT_) + (size_t)bn * (K_) + k0;                   \
            uint32_t sb = smb + (tn & 3) * stageBytes;                          \
            cp_async16(sb + aOff0, Ap + (size_t)lr * (K_) + lc);                \
            cp_async16(sb + aOff1, Ap + (size_t)(lr + 64) * (K_) + lc);         \
            cp_async16(sb + bBase + aOff0, Bp + (size_t)lr * (K_) + lc);        \
            cp_async16(sb + bBase + aOff1, Bp + (size_t)(lr + 64) * (K_) + lc); \
        }                                                                       \
        CP_COMMIT();                                                            \
    }

#define GEMM_PREAMBLE                                  \
    extern __shared__ float smg[];                     \
    const uint32_t smb = smem_u32(smg);                \
    const int tid = threadIdx.x;                       \
    const int wid = tid >> 5;                          \
    const int lane = tid & 31;                         \
    const int g  = lane >> 2;                          \
    const int t4 = lane & 3;                           \
    const int wm = (wid >> 2) * 64;                    \
    const int wn = (wid & 3) * 32;                     \
    const int bm = blockIdx.y * 128;                   \
    const int bn = blockIdx.x * 128;                   \
    const int lr = tid >> 2;                           \
    const int lc = (tid & 3) * 4;                      \
    float c[4][4][4];                                  \
    _Pragma("unroll")                                  \
    for (int mt = 0; mt < 4; mt++)                     \
        _Pragma("unroll")                              \
        for (int nt = 0; nt < 4; nt++)                 \
            _Pragma("unroll")                          \
            for (int r = 0; r < 4; r++) c[mt][nt][r] = 0.0f;

// ---------------------------------------------------------------------------
// Plain GEMM (used for the output projection): fp32 store.
// ---------------------------------------------------------------------------
__global__ __launch_bounds__(256, 2) void tc_gemm2(const float* __restrict__ A,
                                                   const float* __restrict__ BT,
                                                   float* __restrict__ C,
                                                   int M, int N, int K)
{
    GEMM_PREAMBLE
    GEMM_MAINLOOP(A, BT, K)

    #pragma unroll
    for (int mt = 0; mt < 4; mt++) {
        int row = bm + wm + mt * 16 + g;
        #pragma unroll
        for (int nt = 0; nt < 4; nt++) {
            int col = bn + wn + nt * 8 + t4 * 2;
            *(float2*)(C + (size_t)row * N + col) = make_float2(c[mt][nt][0], c[mt][nt][1]);
            *(float2*)(C + (size_t)(row + 8) * N + col) = make_float2(c[mt][nt][2], c[mt][nt][3]);
        }
    }
}

// ---------------------------------------------------------------------------
// Fused QKV GEMM: epilogue applies RoPE (+scale) to q/k regions, tf32-rounds
// everything, stores into the fused [ROWS][3072] buffer.
// q cols [0,2048): rope, scale = 1/sqrt(HD)*log2e
// k cols [2048,2560): rope, scale = 1
// v cols [2560,3072): round only
// Region is uniform per CTA (boundaries 128-aligned).
// ---------------------------------------------------------------------------
__global__ __launch_bounds__(256, 2) void tc_gemm2_qkv(const float* __restrict__ A,
                                                       const float* __restrict__ BT,
                                                       float* __restrict__ C,
                                                       int M, int N, int K)
{
    GEMM_PREAMBLE
    GEMM_MAINLOOP(A, BT, K)

    const bool isV = (bn >= VOFF);
    const float oscale = (bn < KOFF)
        ? 0.08838834764831845f * 1.4426950408889634f : 1.0f;

    #pragma unroll
    for (int nt = 0; nt < 4; nt++) {
        int col = bn + wn + nt * 8 + t4 * 2;
        if (!isV) {
            int p = (col & (HD - 1)) >> 1;
            float freq = exp2f(-(float)p * 0.2076205059304640f);
            #pragma unroll
            for (int mt = 0; mt < 4; mt++) {
                int row = bm + wm + mt * 16 + g;
                uint2 s0, s1;
                rope_pair(c[mt][nt][0], c[mt][nt][1], row & (SEQ - 1), freq,
                          oscale, s0.x, s0.y);
                rope_pair(c[mt][nt][2], c[mt][nt][3], (row + 8) & (SEQ - 1), freq,
                          oscale, s1.x, s1.y);
                *(uint2*)(C + (size_t)row * N + col) = s0;
                *(uint2*)(C + (size_t)(row + 8) * N + col) = s1;
            }
        } else {
            #pragma unroll
            for (int mt = 0; mt < 4; mt++) {
                int row = bm + wm + mt * 16 + g;
                uint2 s0, s1;
                s0.x = f2tf32(c[mt][nt][0]); s0.y = f2tf32(c[mt][nt][1]);
                s1.x = f2tf32(c[mt][nt][2]); s1.y = f2tf32(c[mt][nt][3]);
                *(uint2*)(C + (size_t)row * N + col) = s0;
                *(uint2*)(C + (size_t)(row + 8) * N + col) = s1;
            }
        }
    }
}

// ---------------------------------------------------------------------------
// Tensor-core flash attention (tf32 mma.sync). Reads the fused qkv buffer
// (row stride QKVN); inputs pre-rounded/pre-scaled. Epilogue rounds att.
// ---------------------------------------------------------------------------
#define KS_PAD 132
#define VS_PAD 136
#define PS_PAD 68
#define FLTC_SMEM ((64 * KS_PAD + 64 * VS_PAD + 128 * PS_PAD) * 4)  // 103424 B

__global__ __launch_bounds__(256, 1) void flash_tc(const float* __restrict__ QKV,
                                                   float* __restrict__ Og)
{
    extern __shared__ float smf[];
    float* Ks = smf;                      // [64][132]
    float* Vs = Ks + 64 * KS_PAD;         // [64][136]
    float* Ps = Vs + 64 * VS_PAD;         // [128][68] (also Q staging)

    const int tid = threadIdx.x;
    const int lane = tid & 31;
    const int wid = tid >> 5;
    const int g  = lane >> 2;
    const int t4 = lane & 3;
    const int wm = wid * 16;

    const int b  = blockIdx.z;
    const int h  = blockIdx.y;
    const int q0 = blockIdx.x * 128;
    const int kvh = h >> 2;

    const float* Qb = QKV + (size_t)b * SEQ * QKVN + h * HD;
    const float* Kb = QKV + (size_t)b * SEQ * QKVN + KOFF + kvh * HD;
    const float* Vb = QKV + (size_t)b * SEQ * QKVN + VOFF + kvh * HD;

    // ---- Stage Q into register A-fragments (two 64-col phases) ----
    uint32_t qf[16][4];
    #pragma unroll
    for (int ph = 0; ph < 2; ph++) {
        const int d0 = ph * 64;
        #pragma unroll
        for (int i = 0; i < 8; i++) {
            int idx = tid + 256 * i;
            int r = idx >> 4;
            int c4 = (idx & 15) << 2;
            *(float4*)&Ps[r * PS_PAD + c4] =
                *(const float4*)(Qb + (size_t)(q0 + r) * QKVN + d0 + c4);
        }
        __syncthreads();
        #pragma unroll
        for (int j = 0; j < 8; j++) {
            int ks = ph * 8 + j;
            qf[ks][0] = __float_as_uint(Ps[(wm + g) * PS_PAD + j * 8 + t4]);
            qf[ks][1] = __float_as_uint(Ps[(wm + g + 8) * PS_PAD + j * 8 + t4]);
            qf[ks][2] = __float_as_uint(Ps[(wm + g) * PS_PAD + j * 8 + t4 + 4]);
            qf[ks][3] = __float_as_uint(Ps[(wm + g + 8) * PS_PAD + j * 8 + t4 + 4]);
        }
        __syncthreads();
    }

    float o[16][4];
    #pragma unroll
    for (int nt = 0; nt < 16; nt++)
        #pragma unroll
        for (int r = 0; r < 4; r++) o[nt][r] = 0.0f;
    float mi0 = -1e30f, mi1 = -1e30f, li0 = 0.0f, li1 = 0.0f;

    const int ig0 = q0 + wm + g;
    const int ig1 = ig0 + 8;
    const int ntiles = (q0 >> 6) + 2;

    for (int kt = 0; kt < ntiles; ++kt) {
        const int j0 = kt * 64;

        // ---- Stage K,V: pure copy ----
        #pragma unroll
        for (int i = 0; i < 8; i++) {
            int idx = tid + 256 * i;
            int r = idx >> 5;
            int c4 = (idx & 31) << 2;
            *(float4*)&Ks[r * KS_PAD + c4] =
                *(const float4*)(Kb + (size_t)(j0 + r) * QKVN + c4);
            *(float4*)&Vs[r * VS_PAD + c4] =
                *(const float4*)(Vb + (size_t)(j0 + r) * QKVN + c4);
        }
        __syncthreads();

        // ---- S = Q @ K^T ----
        float sf[8][4];
        #pragma unroll
        for (int nt = 0; nt < 8; nt++)
            #pragma unroll
            for (int r = 0; r < 4; r++) sf[nt][r] = 0.0f;

        #pragma unroll
        for (int ks = 0; ks < 16; ks++) {
            #pragma unroll
            for (int nt = 0; nt < 8; nt++) {
                uint32_t b0 = __float_as_uint(Ks[(nt * 8 + g) * KS_PAD + ks * 8 + t4]);
                uint32_t b1 = __float_as_uint(Ks[(nt * 8 + g) * KS_PAD + ks * 8 + t4 + 4]);
                mma_tf32(sf[nt][0], sf[nt][1], sf[nt][2], sf[nt][3],
                         qf[ks][0], qf[ks][1], qf[ks][2], qf[ks][3], b0, b1);
            }
        }

        // ---- Causal mask ----
        if (kt >= ntiles - 2) {
            #pragma unroll
            for (int nt = 0; nt < 8; nt++) {
                int jg = j0 + nt * 8 + 2 * t4;
                if (jg     > ig0) sf[nt][0] = -1e30f;
                if (jg + 1 > ig0) sf[nt][1] = -1e30f;
                if (jg     > ig1) sf[nt][2] = -1e30f;
                if (jg + 1 > ig1) sf[nt][3] = -1e30f;
            }
        }

        // ---- Online softmax (base 2) ----
        float m0 = -1e30f, m1 = -1e30f;
        #pragma unroll
        for (int nt = 0; nt < 8; nt++) {
            m0 = fmaxf(m0, fmaxf(sf[nt][0], sf[nt][1]));
            m1 = fmaxf(m1, fmaxf(sf[nt][2], sf[nt][3]));
        }
        m0 = fmaxf(m0, __shfl_xor_sync(0xffffffffu, m0, 1));
        m0 = fmaxf(m0, __shfl_xor_sync(0xffffffffu, m0, 2));
        m1 = fmaxf(m1, __shfl_xor_sync(0xffffffffu, m1, 1));
        m1 = fmaxf(m1, __shfl_xor_sync(0xffffffffu, m1, 2));

        float mn0 = fmaxf(mi0, m0);
        float mn1 = fmaxf(mi1, m1);
        float alpha0 = fexp2(mi0 - mn0);
        float alpha1 = fexp2(mi1 - mn1);
        mi0 = mn0; mi1 = mn1;

        float l0 = 0.0f, l1 = 0.0f;
        #pragma unroll
        for (int nt = 0; nt < 8; nt++) {
            float p0 = __uint_as_float(f2tf32(fexp2(sf[nt][0] - mn0)));
            float p1 = __uint_as_float(f2tf32(fexp2(sf[nt][1] - mn0)));
            float p2 = __uint_as_float(f2tf32(fexp2(sf[nt][2] - mn1)));
            float p3 = __uint_as_float(f2tf32(fexp2(sf[nt][3] - mn1)));
            l0 += p0 + p1;
            l1 += p2 + p3;
            *(float2*)&Ps[(wm + g) * PS_PAD + nt * 8 + 2 * t4]     = make_float2(p0, p1);
            *(float2*)&Ps[(wm + g + 8) * PS_PAD + nt * 8 + 2 * t4] = make_float2(p2, p3);
        }
        l0 += __shfl_xor_sync(0xffffffffu, l0, 1);
        l0 += __shfl_xor_sync(0xffffffffu, l0, 2);
        l1 += __shfl_xor_sync(0xffffffffu, l1, 1);
        l1 += __shfl_xor_sync(0xffffffffu, l1, 2);
        li0 = li0 * alpha0 + l0;
        li1 = li1 * alpha1 + l1;

        #pragma unroll
        for (int nt = 0; nt < 16; nt++) {
            o[nt][0] *= alpha0; o[nt][1] *= alpha0;
            o[nt][2] *= alpha1; o[nt][3] *= alpha1;
        }
        __syncwarp();   // P rows are warp-private

        // ---- O += P @ V ----
        #pragma unroll
        for (int ks2 = 0; ks2 < 8; ks2++) {
            uint32_t a0 = __float_as_uint(Ps[(wm + g) * PS_PAD + ks2 * 8 + t4]);
            uint32_t a1 = __float_as_uint(Ps[(wm + g + 8) * PS_PAD + ks2 * 8 + t4]);
            uint32_t a2 = __float_as_uint(Ps[(wm + g) * PS_PAD + ks2 * 8 + t4 + 4]);
            uint32_t a3 = __float_as_uint(Ps[(wm + g + 8) * PS_PAD + ks2 * 8 + t4 + 4]);
            #pragma unroll
            for (int nt = 0; nt < 16; nt++) {
                uint32_t b0 = __float_as_uint(Vs[(ks2 * 8 + t4) * VS_PAD + nt * 8 + g]);
                uint32_t b1 = __float_as_uint(Vs[(ks2 * 8 + t4 + 4) * VS_PAD + nt * 8 + g]);
                mma_tf32(o[nt][0], o[nt][1], o[nt][2], o[nt][3],
                         a0, a1, a2, a3, b0, b1);
            }
        }
        __syncthreads();
    }

    // ---- Epilogue: normalize, round to tf32 (feeds w0 GEMM), store ----
    const float inv0 = 1.0f / li0;
    const float inv1 = 1.0f / li1;
    float* Ob = Og + (size_t)(b * SEQ + q0) * DIM + h * HD;
    #pragma unroll
    for (int nt = 0; nt < 16; nt++) {
        int col = nt * 8 + 2 * t4;
        uint2 s0, s1;
        s0.x = f2tf32(o[nt][0] * inv0); s0.y = f2tf32(o[nt][1] * inv0);
        s1.x = f2tf32(o[nt][2] * inv1); s1.y = f2tf32(o[nt][3] * inv1);
        *(uint2*)(Ob + (size_t)(wm + g) * DIM + col) = s0;
        *(uint2*)(Ob + (size_t)(wm + g + 8) * DIM + col) = s1;
    }
}

// ---------------------------------------------------------------------------
extern "C" void kernel_launch(void* const* d_in, const int* in_sizes, int n_in,
                              void* d_out, int out_size)
{
    const float* x  = (const float*)d_in[0];
    const float* wq = (const float*)d_in[1];
    const float* wk = (const float*)d_in[2];
    const float* wv = (const float*)d_in[3];
    const float* w0 = (const float*)d_in[4];
    float* out = (float*)d_out;

    float *x32, *qkv, *att, *wqkvT, *w0T;
    cudaGetSymbolAddress((void**)&x32,   g_x32);
    cudaGetSymbolAddress((void**)&qkv,   g_qkv);
    cudaGetSymbolAddress((void**)&att,   g_att);
    cudaGetSymbolAddress((void**)&wqkvT, g_wqkvT);
    cudaGetSymbolAddress((void**)&w0T,   g_w0T);

    // Pre-round x; transpose + round weights into fused wqkvT and w0T
    {
        int n4 = ROWS * DIM / 4;
        round_tf32_k<<<(n4 + 255) / 256, 256>>>(x, x32, n4);
        dim3 blk(32, 8);
        transpose_tf32_k<<<dim3(DIM / 32,   DIM / 32), blk>>>(wq, wqkvT, DIM, DIM);
        transpose_tf32_k<<<dim3(KVDIM / 32, DIM / 32), blk>>>(
            wk, wqkvT + (size_t)KOFF * DIM, DIM, KVDIM);
        transpose_tf32_k<<<dim3(KVDIM / 32, DIM / 32), blk>>>(
            wv, wqkvT + (size_t)VOFF * DIM, DIM, KVDIM);
        transpose_tf32_k<<<dim3(DIM / 32,   DIM / 32), blk>>>(w0, w0T, DIM, DIM);
    }

    cudaFuncSetAttribute(tc_gemm2, cudaFuncAttributeMaxDynamicSharedMemorySize,
                         GEMM2_SMEM);
    cudaFuncSetAttribute(tc_gemm2_qkv, cudaFuncAttributeMaxDynamicSharedMemorySize,
                         GEMM2_SMEM);

    // Fused QKV projection + RoPE + tf32 round
    tc_gemm2_qkv<<<dim3(QKVN / 128, ROWS / 128), 256, GEMM2_SMEM>>>(
        x32, wqkvT, qkv, ROWS, QKVN, DIM);

    // Tensor-core flash attention (reads fused buffer)
    cudaFuncSetAttribute(flash_tc, cudaFuncAttributeMaxDynamicSharedMemorySize,
                         FLTC_SMEM);
    flash_tc<<<dim3(SEQ / 128, NH, BATCH), 256, FLTC_SMEM>>>(qkv, att);

    // Output projection
    tc_gemm2<<<dim3(DIM / 128, ROWS / 128), 256, GEMM2_SMEM>>>(
        att, w0T, out, ROWS, DIM, DIM);
}